// round 2
// baseline (speedup 1.0000x reference)
#include <cuda_runtime.h>

// Problem constants
#define BATCH   512
#define SEQ     512
#define EMB     128
#define FILT    128
#define KW      3
#define NCLS    53
#define VOCAB   21128

// Tiling
#define LT      128          // l-tile
#define NTILES  (SEQ / LT)   // 4
#define EC      32           // e-chunk

// smem layout (floats)
#define XS_STRIDE 129                     // conflict-free: bank = tx
#define XS_ELEMS  (130 * XS_STRIDE)       // 16770
#define AS_OFF    16772                   // pad to 16B alignment for float4 As loads
#define AS_ELEMS  (EC * FILT)             // 4096
#define POOL_OFF  (AS_OFF + AS_ELEMS)     // 20868
#define SMEM_FLOATS (POOL_OFF + 3 * FILT) // + pooled[3][128]
#define SMEM_BYTES  (SMEM_FLOATS * 4)     // 85008 B

// Pre-transposed conv weights: Wt[k][e][f] = conv_w[f][e][k]
__device__ float g_Wt[KW][EMB][FILT];

__global__ void transpose_w_kernel(const float* __restrict__ conv_w) {
    int idx = blockIdx.x * blockDim.x + threadIdx.x;
    if (idx < KW * EMB * FILT) {
        int f = idx & (FILT - 1);
        int e = (idx >> 7) & (EMB - 1);
        int k = idx >> 14;
        g_Wt[k][e][f] = conv_w[(f * EMB + e) * KW + k];
    }
}

__global__ __launch_bounds__(256, 2)
void pcnn_fused_kernel(const int*   __restrict__ char_ids,   // [B][SEQ]
                       const int*   __restrict__ pos_e1,     // [B]
                       const int*   __restrict__ pos_e2,     // [B]
                       const float* __restrict__ emb,        // [VOCAB][EMB]
                       const float* __restrict__ conv_b,     // [FILT]
                       const float* __restrict__ fc_w,       // [NCLS][3*FILT]
                       const float* __restrict__ fc_b,       // [NCLS]
                       float*       __restrict__ out)        // [B][NCLS]
{
    extern __shared__ float smem[];
    float*    xs      = smem;                     // [130][129] : xs[p][e], p = l_local+1
    float*    As      = smem + AS_OFF;            // [EC][FILT] : Wt chunk [e][f]
    unsigned* pooledU = (unsigned*)(smem + POOL_OFF); // [3][FILT] as float bits

    const int b  = blockIdx.x;
    const int tx = threadIdx.x;   // l dimension (stride-16 interleave)
    const int ty = threadIdx.y;   // f dimension (8 consecutive filters)
    const int tid = ty * 16 + tx;

    // ---- segment bounds (replicates reference semantics exactly) ----
    const int p1 = pos_e1[b], p2 = pos_e2[b];
    int e1 = min(p1, p2);
    int e2 = max(p1, p2);
    if (e1 == e2) e2 = min(e1 + 1, SEQ);
    const int m1hi = max(e1, 1);        // seg1: l <  m1hi
    const int m3lo = min(e2, SEQ - 1);  // seg3: l >= m3lo

    // init pooled maxima to 0 bits (valid: ReLU outputs >= 0, all masks nonempty)
    for (int i = tid; i < 3 * FILT; i += 256) pooledU[i] = 0u;

    // per-thread bias for its 8 filters
    float bias[8];
    #pragma unroll
    for (int i = 0; i < 8; ++i) bias[i] = conv_b[ty * 8 + i];

    float acc[8][8];

    for (int lt = 0; lt < NTILES; ++lt) {
        const int base = lt * LT;

        #pragma unroll
        for (int i = 0; i < 8; ++i)
            #pragma unroll
            for (int j = 0; j < 8; ++j) acc[i][j] = 0.f;

        // make sure previous tile's readers of xs are done
        __syncthreads();

        // ---- gather embeddings for this tile (+halo) into xs[p][e] ----
        // 130 rows x 32 float4 each; one warp handles one row per step (coalesced)
        for (int v = tid; v < 130 * 32; v += 256) {
            const int p = v >> 5;        // 0..129
            const int c = v & 31;        // float4 lane within row
            const int l = base + p - 1;
            float4 val = make_float4(0.f, 0.f, 0.f, 0.f);
            if (l >= 0 && l < SEQ) {
                const int id = __ldg(&char_ids[b * SEQ + l]);
                val = __ldg(&((const float4*)emb)[id * 32 + c]);
            }
            float* dst = &xs[p * XS_STRIDE + c * 4];
            dst[0] = val.x; dst[1] = val.y; dst[2] = val.z; dst[3] = val.w;
        }
        // (visibility of xs covered by the sync after the first As load below)

        // ---- conv as 3 accumulated GEMMs over k taps, e in chunks of 32 ----
        for (int k = 0; k < KW; ++k) {
            for (int ec = 0; ec < EMB / EC; ++ec) {
                __syncthreads();  // previous As readers done (also fences xs stores)
                {
                    const float4* src = (const float4*)&g_Wt[k][ec * EC][0];
                    float4* dst = (float4*)As;
                    for (int v = tid; v < (EC * FILT) / 4; v += 256)
                        dst[v] = src[v];
                }
                __syncthreads();

                // b operand column base: xs[(tx + 16*j + k)][eglob]
                const float* xcol = &xs[(tx + k) * XS_STRIDE + ec * EC];

                #pragma unroll 4
                for (int e = 0; e < EC; ++e) {
                    const float4 a0 = ((const float4*)&As[e * FILT + ty * 8])[0];
                    const float4 a1 = ((const float4*)&As[e * FILT + ty * 8])[1];
                    const float av[8] = {a0.x, a0.y, a0.z, a0.w,
                                         a1.x, a1.y, a1.z, a1.w};
                    float bb[8];
                    #pragma unroll
                    for (int j = 0; j < 8; ++j)
                        bb[j] = xcol[j * (16 * XS_STRIDE) + e];
                    #pragma unroll
                    for (int i = 0; i < 8; ++i)
                        #pragma unroll
                        for (int j = 0; j < 8; ++j)
                            acc[i][j] = fmaf(av[i], bb[j], acc[i][j]);
                }
            }
        }

        // ---- epilogue: bias + ReLU + 3-segment running max (smem atomics) ----
        #pragma unroll
        for (int i = 0; i < 8; ++i) {
            const int f = ty * 8 + i;
            #pragma unroll
            for (int j = 0; j < 8; ++j) {
                const int l = base + tx + 16 * j;
                float v = acc[i][j] + bias[i];
                v = v > 0.f ? v : 0.f;
                const unsigned uv = __float_as_uint(v);  // monotonic for v >= 0
                if (l < m1hi)             atomicMax(&pooledU[f], uv);
                if (l >= e1 && l < e2)    atomicMax(&pooledU[FILT + f], uv);
                if (l >= m3lo)            atomicMax(&pooledU[2 * FILT + f], uv);
            }
        }
    }

    __syncthreads();  // all pooled maxima visible

    // ---- FC: out[b][c] = pooled . fc_w[c] + fc_b[c] ----
    if (tid < NCLS) {
        float a = fc_b[tid];
        const float* w = &fc_w[tid * 3 * FILT];
        #pragma unroll 8
        for (int i = 0; i < 3 * FILT; ++i)
            a = fmaf(__uint_as_float(pooledU[i]), __ldg(&w[i]), a);
        out[b * NCLS + tid] = a;
    }
}

extern "C" void kernel_launch(void* const* d_in, const int* in_sizes, int n_in,
                              void* d_out, int out_size) {
    const int*   char_ids = (const int*)  d_in[0];
    const int*   pos_e1   = (const int*)  d_in[1];
    const int*   pos_e2   = (const int*)  d_in[2];
    const float* emb      = (const float*)d_in[3];
    const float* conv_w   = (const float*)d_in[4];
    const float* conv_b   = (const float*)d_in[5];
    const float* fc_w     = (const float*)d_in[6];
    const float* fc_b     = (const float*)d_in[7];
    float* out = (float*)d_out;

    cudaFuncSetAttribute(pcnn_fused_kernel,
                         cudaFuncAttributeMaxDynamicSharedMemorySize, SMEM_BYTES);

    transpose_w_kernel<<<(KW * EMB * FILT + 255) / 256, 256>>>(conv_w);
    pcnn_fused_kernel<<<BATCH, dim3(16, 16), SMEM_BYTES>>>(
        char_ids, pos_e1, pos_e2, emb, conv_b, fc_w, fc_b, out);
}

// round 4
// speedup vs baseline: 1.0436x; 1.0436x over previous
#include <cuda_runtime.h>
#include <cstdint>

// Problem constants
#define BATCH   512
#define SEQ     512
#define EMB     128
#define FILT    128
#define KW      3
#define NCLS    53
#define VOCAB   21128

// Tiling
#define LT      128          // l-tile
#define NTILES  (SEQ / LT)   // 4
#define EC      64           // e-chunk (As = 64x128 floats = 32KB)

// smem layout (floats)
#define XS_STRIDE 129                     // conflict-free: bank = tx
#define AS_OFF    16772                   // 130*129=16770, padded to 16B align
#define AS_ELEMS  (EC * FILT)             // 8192
#define POOL_OFF  (AS_OFF + AS_ELEMS)     // 24964
#define SMEM_FLOATS (POOL_OFF + 3 * FILT)
#define SMEM_BYTES  (SMEM_FLOATS * 4)     // ~101392 B -> occ 2 still fits

// packed fp32x2 helpers (SASS FFMA2 path — ptxas won't emit from C++)
#define FMA2(d, a, b) asm("fma.rn.f32x2 %0, %1, %2, %0;" : "+l"(d) : "l"(a), "l"(b))
#define SPLAT2(d, x)  asm("mov.b64 %0, {%1, %1};" : "=l"(d) : "f"(x))
#define UNPACK2(lo, hi, v) asm("mov.b64 {%0, %1}, %2;" : "=f"(lo), "=f"(hi) : "l"(v))

// Pre-transposed conv weights: Wt[k][e][f] = conv_w[f][e][k]
__device__ float g_Wt[KW][EMB][FILT];

__global__ void transpose_w_kernel(const float* __restrict__ conv_w) {
    int idx = blockIdx.x * blockDim.x + threadIdx.x;
    if (idx < KW * EMB * FILT) {
        int f = idx & (FILT - 1);
        int e = (idx >> 7) & (EMB - 1);
        int k = idx >> 14;
        g_Wt[k][e][f] = conv_w[(f * EMB + e) * KW + k];
    }
}

__global__ __launch_bounds__(256, 2)
void pcnn_fused_kernel(const int*   __restrict__ char_ids,   // [B][SEQ]
                       const int*   __restrict__ pos_e1,     // [B]
                       const int*   __restrict__ pos_e2,     // [B]
                       const float* __restrict__ emb,        // [VOCAB][EMB]
                       const float* __restrict__ conv_b,     // [FILT]
                       const float* __restrict__ fc_w,       // [NCLS][3*FILT]
                       const float* __restrict__ fc_b,       // [NCLS]
                       float*       __restrict__ out)        // [B][NCLS]
{
    extern __shared__ float smem[];
    float*    xs      = smem;                     // [130][129] : xs[p][e], p = l_local+1
    float*    As      = smem + AS_OFF;            // [EC][FILT] : Wt chunk [e][f]
    unsigned* pooledU = (unsigned*)(smem + POOL_OFF); // [3][FILT] as float bits

    const int b  = blockIdx.x;
    const int tx = threadIdx.x;   // l dimension (stride-16 interleave)
    const int ty = threadIdx.y;   // f dimension (8 consecutive filters)
    const int tid = ty * 16 + tx;

    // ---- segment bounds (replicates reference semantics exactly) ----
    const int p1 = pos_e1[b], p2 = pos_e2[b];
    int e1 = min(p1, p2);
    int e2 = max(p1, p2);
    if (e1 == e2) e2 = min(e1 + 1, SEQ);
    const int m1hi = max(e1, 1);        // seg1: l <  m1hi
    const int m3lo = min(e2, SEQ - 1);  // seg3: l >= m3lo

    // init pooled maxima to 0 bits (valid: ReLU outputs >= 0, all masks nonempty)
    for (int i = tid; i < 3 * FILT; i += 256) pooledU[i] = 0u;

    // per-thread bias for its 8 filters
    float bias[8];
    #pragma unroll
    for (int i = 0; i < 8; ++i) bias[i] = conv_b[ty * 8 + i];

    // acc2[i2][j]: filter-pair i2 (filters ty*8+2*i2, +1) x l-slot j, packed fp32x2
    uint64_t acc2[4][8];

    for (int lt = 0; lt < NTILES; ++lt) {
        const int base = lt * LT;

        #pragma unroll
        for (int i = 0; i < 4; ++i)
            #pragma unroll
            for (int j = 0; j < 8; ++j) acc2[i][j] = 0ull;

        // make sure previous tile's readers of xs are done
        __syncthreads();

        // ---- gather embeddings for this tile (+halo) into xs[p][e] ----
        for (int v = tid; v < 130 * 32; v += 256) {
            const int p = v >> 5;        // 0..129
            const int c = v & 31;        // float4 lane within row
            const int l = base + p - 1;
            float4 val = make_float4(0.f, 0.f, 0.f, 0.f);
            if (l >= 0 && l < SEQ) {
                const int id = __ldg(&char_ids[b * SEQ + l]);
                val = __ldg(&((const float4*)emb)[id * 32 + c]);
            }
            float* dst = &xs[p * XS_STRIDE + c * 4];
            dst[0] = val.x; dst[1] = val.y; dst[2] = val.z; dst[3] = val.w;
        }

        // ---- conv as 3 accumulated GEMMs over k taps, e in chunks of EC ----
        for (int k = 0; k < KW; ++k) {
            for (int ec = 0; ec < EMB / EC; ++ec) {
                __syncthreads();  // previous As readers done (also fences xs stores)
                {
                    const float4* src = (const float4*)&g_Wt[k][ec * EC][0];
                    float4* dst = (float4*)As;
                    for (int v = tid; v < (EC * FILT) / 4; v += 256)
                        dst[v] = src[v];
                }
                __syncthreads();

                const float* xcol = &xs[(tx + k) * XS_STRIDE + ec * EC];

                #pragma unroll 4
                for (int e = 0; e < EC; ++e) {
                    // A pairs: 4 x fp32x2 directly from As row (32B, 16B-aligned)
                    const uint64_t* arow =
                        (const uint64_t*)&As[e * FILT + ty * 8];
                    const uint64_t av0 = arow[0], av1 = arow[1],
                                   av2 = arow[2], av3 = arow[3];
                    // x splats
                    uint64_t bb2[8];
                    #pragma unroll
                    for (int j = 0; j < 8; ++j) {
                        const float bv = xcol[j * (16 * XS_STRIDE) + e];
                        SPLAT2(bb2[j], bv);
                    }
                    #pragma unroll
                    for (int j = 0; j < 8; ++j) {
                        FMA2(acc2[0][j], av0, bb2[j]);
                        FMA2(acc2[1][j], av1, bb2[j]);
                        FMA2(acc2[2][j], av2, bb2[j]);
                        FMA2(acc2[3][j], av3, bb2[j]);
                    }
                }
            }
        }

        // ---- epilogue: bias + ReLU + 3-segment running max (smem atomics) ----
        #pragma unroll
        for (int i2 = 0; i2 < 4; ++i2) {
            const int f0 = ty * 8 + 2 * i2;
            #pragma unroll
            for (int j = 0; j < 8; ++j) {
                const int l = base + tx + 16 * j;
                float vlo, vhi;
                UNPACK2(vlo, vhi, acc2[i2][j]);
                vlo += bias[2 * i2];     vlo = vlo > 0.f ? vlo : 0.f;
                vhi += bias[2 * i2 + 1]; vhi = vhi > 0.f ? vhi : 0.f;
                const unsigned ulo = __float_as_uint(vlo);
                const unsigned uhi = __float_as_uint(vhi);
                if (l < m1hi) {
                    atomicMax(&pooledU[f0], ulo);
                    atomicMax(&pooledU[f0 + 1], uhi);
                }
                if (l >= e1 && l < e2) {
                    atomicMax(&pooledU[FILT + f0], ulo);
                    atomicMax(&pooledU[FILT + f0 + 1], uhi);
                }
                if (l >= m3lo) {
                    atomicMax(&pooledU[2 * FILT + f0], ulo);
                    atomicMax(&pooledU[2 * FILT + f0 + 1], uhi);
                }
            }
        }
    }

    __syncthreads();  // all pooled maxima visible

    // ---- FC: out[b][c] = pooled . fc_w[c] + fc_b[c] ----
    if (tid < NCLS) {
        float a = fc_b[tid];
        const float* w = &fc_w[tid * 3 * FILT];
        #pragma unroll 8
        for (int i = 0; i < 3 * FILT; ++i)
            a = fmaf(__uint_as_float(pooledU[i]), __ldg(&w[i]), a);
        out[b * NCLS + tid] = a;
    }
}

extern "C" void kernel_launch(void* const* d_in, const int* in_sizes, int n_in,
                              void* d_out, int out_size) {
    const int*   char_ids = (const int*)  d_in[0];
    const int*   pos_e1   = (const int*)  d_in[1];
    const int*   pos_e2   = (const int*)  d_in[2];
    const float* emb      = (const float*)d_in[3];
    const float* conv_w   = (const float*)d_in[4];
    const float* conv_b   = (const float*)d_in[5];
    const float* fc_w     = (const float*)d_in[6];
    const float* fc_b     = (const float*)d_in[7];
    float* out = (float*)d_out;

    cudaFuncSetAttribute(pcnn_fused_kernel,
                         cudaFuncAttributeMaxDynamicSharedMemorySize, SMEM_BYTES);

    transpose_w_kernel<<<(KW * EMB * FILT + 255) / 256, 256>>>(conv_w);
    pcnn_fused_kernel<<<BATCH, dim3(16, 16), SMEM_BYTES>>>(
        char_ids, pos_e1, pos_e2, emb, conv_b, fc_w, fc_b, out);
}

// round 8
// speedup vs baseline: 4.2858x; 4.1067x over previous
#include <cuda_runtime.h>
#include <cuda_fp16.h>
#include <cstdint>

#define BATCH 512
#define SEQ   512
#define EMB   128
#define FILT  128
#define KW    3
#define NCLS  53

// ---- smem layout (bytes) ----
#define WS_OFF   0                 // W fp16 [3][128 f][128 e], row=256B, chunk-swizzled
#define WS_BYTES 98304
#define XS_OFF   98304             // X fp16 [130 rows][128 e], row=256B, chunk-swizzled
#define XS_BYTES 33280
#define POOL_OFF 131584            // uint [3][128]
#define MBAR_OFF 133120
#define SMEM_BYTES 133184

// pre-swizzled fp16 weights in global: g_Wh[k*16384 + f*128 + ((e>>3)^(f&7))*8 + (e&7)]
__device__ __align__(16) __half g_Wh[KW * FILT * EMB];

__device__ __forceinline__ uint32_t smem_u32(const void* p) {
    uint32_t a;
    asm("{ .reg .u64 t; cvta.to.shared.u64 t, %1; cvt.u32.u64 %0, t; }" : "=r"(a) : "l"(p));
    return a;
}

#define MBAR_INIT(a, c) asm volatile("mbarrier.init.shared.b64 [%0], %1;" :: "r"(a), "r"(c) : "memory")
#define MBAR_EXPECT_TX(a, n) asm volatile("mbarrier.arrive.expect_tx.shared.b64 _, [%0], %1;" :: "r"(a), "r"(n) : "memory")
#define MBAR_WAIT(a, p) do { \
    uint32_t _m = (a); uint32_t _p = (p); \
    asm volatile("{\n\t.reg .pred P;\n\tWL_%=:\n\t" \
        "mbarrier.try_wait.parity.acquire.cta.shared::cta.b64 P, [%0], %1, 0x989680;\n\t" \
        "@P bra.uni WD_%=;\n\tbra.uni WL_%=;\n\tWD_%=:\n\t}" :: "r"(_m), "r"(_p) : "memory"); \
} while (0)

#define BULK_G2S(dst, src, nbytes, mbar) \
    asm volatile("cp.async.bulk.shared::cluster.global.mbarrier::complete_tx::bytes [%0], [%1], %2, [%3];" \
        :: "r"(dst), "l"(src), "r"(nbytes), "r"(mbar) : "memory")

#define LDSM_X4(r0, r1, r2, r3, a) \
    asm volatile("ldmatrix.sync.aligned.m8n8.x4.shared.b16 {%0,%1,%2,%3}, [%4];" \
        : "=r"(r0), "=r"(r1), "=r"(r2), "=r"(r3) : "r"(a))

#define MMA16816(c, a, b0, b1) \
    asm volatile("mma.sync.aligned.m16n8k16.row.col.f32.f16.f16.f32 " \
        "{%0,%1,%2,%3}, {%4,%5,%6,%7}, {%8,%9}, {%0,%1,%2,%3};" \
        : "+f"((c)[0]), "+f"((c)[1]), "+f"((c)[2]), "+f"((c)[3]) \
        : "r"((a)[0]), "r"((a)[1]), "r"((a)[2]), "r"((a)[3]), "r"(b0), "r"(b1))

// ---------------- prep: convert + swizzle weights ----------------
__global__ void prep_w_kernel(const float* __restrict__ conv_w) {
    int idx = blockIdx.x * blockDim.x + threadIdx.x;
    if (idx >= KW * FILT * EMB) return;
    int k = idx / (FILT * EMB);
    int rem = idx - k * FILT * EMB;
    int f = rem >> 7, e = rem & 127;
    float w = conv_w[(f * EMB + e) * KW + k];
    int dst = k * 16384 + f * 128 + (((e >> 3) ^ (f & 7)) << 3) + (e & 7);
    g_Wh[dst] = __float2half_rn(w);
}

// ---------------- main kernel: one CTA per batch ----------------
__global__ __launch_bounds__(512, 1)
void pcnn_hmma_kernel(const int*   __restrict__ char_ids,
                      const int*   __restrict__ pos_e1,
                      const int*   __restrict__ pos_e2,
                      const float* __restrict__ emb,
                      const float* __restrict__ conv_b,
                      const float* __restrict__ fc_w,
                      const float* __restrict__ fc_b,
                      float*       __restrict__ out)
{
    extern __shared__ char smem[];
    const uint32_t sb = smem_u32(smem);
    const int tid  = threadIdx.x;
    const int w    = tid >> 5;
    const int lane = tid & 31;
    const int b    = blockIdx.x;

    const int wf = w & 3;   // f-tile: f in [wf*32, wf*32+32)
    const int wl = w >> 2;  // l-tile: l_local in [wl*32, wl*32+32)

    unsigned* pooled = (unsigned*)(smem + POOL_OFF);
    const uint32_t mbar = sb + MBAR_OFF;

    // kick off W bulk copy (global, pre-swizzled -> smem) + init pooled
    if (tid == 0) {
        MBAR_INIT(mbar, 1);
        MBAR_EXPECT_TX(mbar, WS_BYTES);
        BULK_G2S(sb + WS_OFF, (uint64_t)&g_Wh[0], WS_BYTES, mbar);
    }
    for (int i = tid; i < 3 * FILT; i += 512) pooled[i] = 0u;

    // segment bounds
    const int p1 = pos_e1[b], p2 = pos_e2[b];
    int e1 = min(p1, p2), e2 = max(p1, p2);
    if (e1 == e2) e2 = min(e1 + 1, SEQ);
    const int m1hi = max(e1, 1);
    const int m3lo = min(e2, SEQ - 1);

    // per-thread epilogue constants
    const int rowc = lane >> 2;
    const int colc = (lane & 3) * 2;
    float biasv[4];
    #pragma unroll
    for (int i = 0; i < 4; ++i)
        biasv[i] = conv_b[wf * 32 + (i >> 1) * 16 + rowc + (i & 1) * 8];
    float rm[4][3];
    #pragma unroll
    for (int i = 0; i < 4; ++i) { rm[i][0] = 0.f; rm[i][1] = 0.f; rm[i][2] = 0.f; }

    // ldmatrix lane-address components
    // A (row-major 16x16): row = lane&15, col-chunk = lane>>4
    const int a_row = lane & 15;
    const int a_cg  = lane >> 4;
    // B (B^T row-major, x4 over n16): n-row = (lane&7) + 8*(lane>>4), k-chunk = (lane>>3)&1
    const int b_r  = (lane & 7) + ((lane >> 4) << 3);
    const int b_kc = (lane >> 3) & 1;

    bool w_waited = false;

    #pragma unroll 1
    for (int pass = 0; pass < 4; ++pass) {
        const int pbase = pass * 128;
        __syncthreads();   // previous pass done reading Xs

        // ---- gather X tile (+halo) into Xs: rows p=0..129 (l = pbase+p-1) ----
        for (int v = tid; v < 130 * 16; v += 512) {
            const int p = v >> 4;
            const int c = v & 15;         // 16B chunk (8 e-values)
            const int l = pbase + p - 1;
            uint4 st = make_uint4(0u, 0u, 0u, 0u);
            if (l >= 0 && l < SEQ) {
                const int id = __ldg(&char_ids[b * SEQ + l]);
                const float4* src = (const float4*)(emb + (size_t)id * EMB) + c * 2;
                const float4 x0 = __ldg(src);
                const float4 x1 = __ldg(src + 1);
                __half2 h0 = __floats2half2_rn(x0.x, x0.y);
                __half2 h1 = __floats2half2_rn(x0.z, x0.w);
                __half2 h2 = __floats2half2_rn(x1.x, x1.y);
                __half2 h3 = __floats2half2_rn(x1.z, x1.w);
                st.x = *(uint32_t*)&h0; st.y = *(uint32_t*)&h1;
                st.z = *(uint32_t*)&h2; st.w = *(uint32_t*)&h3;
            }
            *(uint4*)(smem + XS_OFF + p * 256 + ((c ^ (p & 7)) << 4)) = st;
        }
        __syncthreads();
        if (!w_waited) { MBAR_WAIT(mbar, 0u); w_waited = true; }

        // ---- GEMM: C[32f x 32l] += sum_k sum_e W[k] * X(shifted by k) ----
        float acc[2][4][4];
        #pragma unroll
        for (int mt = 0; mt < 2; ++mt)
            #pragma unroll
            for (int nt = 0; nt < 4; ++nt)
                #pragma unroll
                for (int i = 0; i < 4; ++i) acc[mt][nt][i] = 0.f;

        #pragma unroll
        for (int k = 0; k < KW; ++k) {
            // A bases per mt (swizzle key = f&7, constant per thread/mt)
            uint32_t aBase[2]; int aS[2];
            #pragma unroll
            for (int mt = 0; mt < 2; ++mt) {
                const int f = wf * 32 + mt * 16 + a_row;
                aBase[mt] = sb + WS_OFF + (uint32_t)(k * 128 + f) * 256u;
                aS[mt] = f & 7;
            }
            // B base: p = wl*32 + nt16*16 + b_r + k  (nt16*16 doesn't change p&7)
            const int p0 = wl * 32 + b_r + k;
            const uint32_t bBase = sb + XS_OFF + (uint32_t)p0 * 256u;
            const int bS = p0 & 7;

            #pragma unroll
            for (int ec = 0; ec < 8; ++ec) {
                uint32_t a0[4], a1[4], bb0[4], bb1[4];
                const int ca = ec * 2 + a_cg;
                const int cb = ec * 2 + b_kc;
                LDSM_X4(a0[0], a0[1], a0[2], a0[3],
                        aBase[0] + (uint32_t)((ca ^ aS[0]) << 4));
                LDSM_X4(a1[0], a1[1], a1[2], a1[3],
                        aBase[1] + (uint32_t)((ca ^ aS[1]) << 4));
                const uint32_t bsw = (uint32_t)((cb ^ bS) << 4);
                LDSM_X4(bb0[0], bb0[1], bb0[2], bb0[3], bBase + bsw);
                LDSM_X4(bb1[0], bb1[1], bb1[2], bb1[3], bBase + 4096u + bsw);

                MMA16816(acc[0][0], a0, bb0[0], bb0[1]);
                MMA16816(acc[0][1], a0, bb0[2], bb0[3]);
                MMA16816(acc[0][2], a0, bb1[0], bb1[1]);
                MMA16816(acc[0][3], a0, bb1[2], bb1[3]);
                MMA16816(acc[1][0], a1, bb0[0], bb0[1]);
                MMA16816(acc[1][1], a1, bb0[2], bb0[3]);
                MMA16816(acc[1][2], a1, bb1[0], bb1[1]);
                MMA16816(acc[1][3], a1, bb1[2], bb1[3]);
            }
        }

        // ---- epilogue: bias + ReLU + running segment max (registers) ----
        #pragma unroll
        for (int mt = 0; mt < 2; ++mt)
            #pragma unroll
            for (int nt = 0; nt < 4; ++nt)
                #pragma unroll
                for (int e = 0; e < 4; ++e) {
                    const int half = e >> 1;
                    const int idx = mt * 2 + half;
                    float v = acc[mt][nt][e] + biasv[idx];
                    v = fmaxf(v, 0.f);
                    const int l = pbase + wl * 32 + nt * 8 + colc + (e & 1);
                    if (l < m1hi)          rm[idx][0] = fmaxf(rm[idx][0], v);
                    if (l >= e1 && l < e2) rm[idx][1] = fmaxf(rm[idx][1], v);
                    if (l >= m3lo)         rm[idx][2] = fmaxf(rm[idx][2], v);
                }
    }

    // ---- reduce per-thread maxima -> pooled ----
    #pragma unroll
    for (int i = 0; i < 4; ++i) {
        const int f = wf * 32 + (i >> 1) * 16 + rowc + (i & 1) * 8;
        atomicMax(&pooled[f],            __float_as_uint(rm[i][0]));
        atomicMax(&pooled[FILT + f],     __float_as_uint(rm[i][1]));
        atomicMax(&pooled[2 * FILT + f], __float_as_uint(rm[i][2]));
    }
    __syncthreads();

    // ---- FC ----
    if (tid < NCLS) {
        float a = fc_b[tid];
        const float* wv = &fc_w[tid * 3 * FILT];
        #pragma unroll 8
        for (int i = 0; i < 3 * FILT; ++i)
            a = fmaf(__uint_as_float(pooled[i]), __ldg(&wv[i]), a);
        out[b * NCLS + tid] = a;
    }
}

extern "C" void kernel_launch(void* const* d_in, const int* in_sizes, int n_in,
                              void* d_out, int out_size) {
    const int*   char_ids = (const int*)  d_in[0];
    const int*   pos_e1   = (const int*)  d_in[1];
    const int*   pos_e2   = (const int*)  d_in[2];
    const float* emb      = (const float*)d_in[3];
    const float* conv_w   = (const float*)d_in[4];
    const float* conv_b   = (const float*)d_in[5];
    const float* fc_w     = (const float*)d_in[6];
    const float* fc_b     = (const float*)d_in[7];
    float* out = (float*)d_out;

    cudaFuncSetAttribute(pcnn_hmma_kernel,
                         cudaFuncAttributeMaxDynamicSharedMemorySize, SMEM_BYTES);

    prep_w_kernel<<<(KW * FILT * EMB + 255) / 256, 256>>>(conv_w);
    pcnn_hmma_kernel<<<BATCH, 512, SMEM_BYTES>>>(
        char_ids, pos_e1, pos_e2, emb, conv_b, fc_w, fc_b, out);
}

// round 9
// speedup vs baseline: 4.9163x; 1.1471x over previous
#include <cuda_runtime.h>
#include <cuda_fp16.h>
#include <cstdint>

#define BATCH 512
#define SEQ   512
#define EMB   128
#define FILT  128
#define KW    3
#define NCLS  53

// ---- smem layout (bytes) ----
#define WS_OFF   0                 // W ring: 2 x 32KB (one tap each), chunk-swizzled
#define WS_BYTES 65536
#define XS_OFF   65536             // X fp16 [66 rows][128 e], row=256B, chunk-swizzled
#define XS_BYTES 16896
#define POOL_OFF 82432             // uint [3][128]
#define MBAR_OFF 83968             // 2 x 8B load mbarriers
#define SMEM_BYTES 84000

// pre-swizzled fp16 weights, tap-major: g_Wh[k*16384 + f*128 + ((e>>3)^(f&7))*8 + (e&7)]
__device__ __align__(16) __half g_Wh[KW * FILT * EMB];

__device__ __forceinline__ uint32_t smem_u32(const void* p) {
    uint32_t a;
    asm("{ .reg .u64 t; cvta.to.shared.u64 t, %1; cvt.u32.u64 %0, t; }" : "=r"(a) : "l"(p));
    return a;
}

#define MBAR_INIT(a, c) asm volatile("mbarrier.init.shared.b64 [%0], %1;" :: "r"(a), "r"(c) : "memory")
#define MBAR_EXPECT_TX(a, n) asm volatile("mbarrier.arrive.expect_tx.shared.b64 _, [%0], %1;" :: "r"(a), "r"(n) : "memory")
#define MBAR_WAIT(a, p) do { \
    uint32_t _m = (a); uint32_t _p = (p); \
    asm volatile("{\n\t.reg .pred P;\n\tWL_%=:\n\t" \
        "mbarrier.try_wait.parity.acquire.cta.shared::cta.b64 P, [%0], %1, 0x989680;\n\t" \
        "@P bra.uni WD_%=;\n\tbra.uni WL_%=;\n\tWD_%=:\n\t}" :: "r"(_m), "r"(_p) : "memory"); \
} while (0)

#define BULK_G2S(dst, src, nbytes, mbar) \
    asm volatile("cp.async.bulk.shared::cluster.global.mbarrier::complete_tx::bytes [%0], [%1], %2, [%3];" \
        :: "r"(dst), "l"(src), "r"(nbytes), "r"(mbar) : "memory")

#define LDSM_X4(r0, r1, r2, r3, a) \
    asm volatile("ldmatrix.sync.aligned.m8n8.x4.shared.b16 {%0,%1,%2,%3}, [%4];" \
        : "=r"(r0), "=r"(r1), "=r"(r2), "=r"(r3) : "r"(a))

#define MMA16816(c, a, b0, b1) \
    asm volatile("mma.sync.aligned.m16n8k16.row.col.f32.f16.f16.f32 " \
        "{%0,%1,%2,%3}, {%4,%5,%6,%7}, {%8,%9}, {%0,%1,%2,%3};" \
        : "+f"((c)[0]), "+f"((c)[1]), "+f"((c)[2]), "+f"((c)[3]) \
        : "r"((a)[0]), "r"((a)[1]), "r"((a)[2]), "r"((a)[3]), "r"(b0), "r"(b1))

// ---------------- prep: convert + swizzle weights ----------------
__global__ void prep_w_kernel(const float* __restrict__ conv_w) {
    int idx = blockIdx.x * blockDim.x + threadIdx.x;
    if (idx >= KW * FILT * EMB) return;
    int k = idx / (FILT * EMB);
    int rem = idx - k * FILT * EMB;
    int f = rem >> 7, e = rem & 127;
    float w = conv_w[(f * EMB + e) * KW + k];
    int dst = k * 16384 + f * 128 + (((e >> 3) ^ (f & 7)) << 3) + (e & 7);
    g_Wh[dst] = __float2half_rn(w);
}

// ---------------- main kernel: one CTA per batch, 2 CTAs/SM ----------------
__global__ __launch_bounds__(256, 2)
void pcnn_hmma_kernel(const int*   __restrict__ char_ids,
                      const int*   __restrict__ pos_e1,
                      const int*   __restrict__ pos_e2,
                      const float* __restrict__ emb,
                      const float* __restrict__ conv_b,
                      const float* __restrict__ fc_w,
                      const float* __restrict__ fc_b,
                      float*       __restrict__ out)
{
    extern __shared__ char smem[];
    const uint32_t sb = smem_u32(smem);
    const int tid  = threadIdx.x;
    const int w    = tid >> 5;
    const int lane = tid & 31;
    const int b    = blockIdx.x;

    const int wf = w & 3;   // f-tile: f in [wf*32, wf*32+32)
    const int wl = w >> 2;  // l-tile within pass: l_local in [wl*32, wl*32+32)

    unsigned* pooled = (unsigned*)(smem + POOL_OFF);
    const uint32_t ld_mb[2] = {sb + MBAR_OFF, sb + MBAR_OFF + 8};

    if (tid == 0) {
        MBAR_INIT(ld_mb[0], 1);
        MBAR_INIT(ld_mb[1], 1);
    }
    for (int i = tid; i < 3 * FILT; i += 256) pooled[i] = 0u;
    __syncthreads();

    // prime the W ring: loads n=0 (tap0 -> buf0), n=1 (tap1 -> buf1)
    if (tid == 0) {
        MBAR_EXPECT_TX(ld_mb[0], 32768u);
        BULK_G2S(sb + WS_OFF, (uint64_t)&g_Wh[0], 32768u, ld_mb[0]);
        MBAR_EXPECT_TX(ld_mb[1], 32768u);
        BULK_G2S(sb + WS_OFF + 32768u, (uint64_t)&g_Wh[16384], 32768u, ld_mb[1]);
    }

    // segment bounds
    const int p1 = pos_e1[b], p2 = pos_e2[b];
    int e1 = min(p1, p2), e2 = max(p1, p2);
    if (e1 == e2) e2 = min(e1 + 1, SEQ);
    const int m1hi = max(e1, 1);
    const int m3lo = min(e2, SEQ - 1);

    // per-thread epilogue constants
    const int rowc = lane >> 2;
    const int colc = (lane & 3) * 2;
    float biasv[4];
    #pragma unroll
    for (int i = 0; i < 4; ++i)
        biasv[i] = conv_b[wf * 32 + (i >> 1) * 16 + rowc + (i & 1) * 8];
    float rm[4][3];
    #pragma unroll
    for (int i = 0; i < 4; ++i) { rm[i][0] = 0.f; rm[i][1] = 0.f; rm[i][2] = 0.f; }

    // ldmatrix lane-address components
    const int a_row = lane & 15;          // A: row within 16
    const int a_cg  = lane >> 4;          // A: col-chunk
    const int b_r  = (lane & 7) + ((lane >> 4) << 3);  // B: n-row
    const int b_kc = (lane >> 3) & 1;                   // B: k-chunk

    #pragma unroll 1
    for (int pass = 0; pass < 8; ++pass) {
        const int pbase = pass * 64;

        // ---- gather X tile (+halo) into Xs: rows p=0..65 (l = pbase+p-1) ----
        for (int v = tid; v < 66 * 16; v += 256) {
            const int p = v >> 4;
            const int c = v & 15;         // 16B chunk (8 e-values)
            const int l = pbase + p - 1;
            uint4 st = make_uint4(0u, 0u, 0u, 0u);
            if (l >= 0 && l < SEQ) {
                const int id = __ldg(&char_ids[b * SEQ + l]);
                const float4* src = (const float4*)(emb + (size_t)id * EMB) + c * 2;
                const float4 x0 = __ldg(src);
                const float4 x1 = __ldg(src + 1);
                __half2 h0 = __floats2half2_rn(x0.x, x0.y);
                __half2 h1 = __floats2half2_rn(x0.z, x0.w);
                __half2 h2 = __floats2half2_rn(x1.x, x1.y);
                __half2 h3 = __floats2half2_rn(x1.z, x1.w);
                st.x = *(uint32_t*)&h0; st.y = *(uint32_t*)&h1;
                st.z = *(uint32_t*)&h2; st.w = *(uint32_t*)&h3;
            }
            *(uint4*)(smem + XS_OFF + p * 256 + ((c ^ (p & 7)) << 4)) = st;
        }
        __syncthreads();

        // ---- GEMM: C[32f x 32l] += sum_k sum_e W[k] * X(shifted by k) ----
        float acc[2][4][4];
        #pragma unroll
        for (int mt = 0; mt < 2; ++mt)
            #pragma unroll
            for (int nt = 0; nt < 4; ++nt)
                #pragma unroll
                for (int i = 0; i < 4; ++i) acc[mt][nt][i] = 0.f;

        #pragma unroll
        for (int k = 0; k < KW; ++k) {
            const int n = pass * 3 + k;       // global load index
            const int buf = n & 1;
            MBAR_WAIT(ld_mb[buf], (uint32_t)((n >> 1) & 1));

            const uint32_t wsBase = sb + WS_OFF + (uint32_t)buf * 32768u;
            uint32_t aBase[2]; int aS[2];
            #pragma unroll
            for (int mt = 0; mt < 2; ++mt) {
                const int f = wf * 32 + mt * 16 + a_row;
                aBase[mt] = wsBase + (uint32_t)f * 256u;
                aS[mt] = f & 7;
            }
            const int p0 = wl * 32 + b_r + k;
            const uint32_t bBase = sb + XS_OFF + (uint32_t)p0 * 256u;
            const int bS = p0 & 7;

            #pragma unroll
            for (int ec = 0; ec < 8; ++ec) {
                uint32_t a0[4], a1[4], bb0[4], bb1[4];
                const int ca = ec * 2 + a_cg;
                const int cb = ec * 2 + b_kc;
                LDSM_X4(a0[0], a0[1], a0[2], a0[3],
                        aBase[0] + (uint32_t)((ca ^ aS[0]) << 4));
                LDSM_X4(a1[0], a1[1], a1[2], a1[3],
                        aBase[1] + (uint32_t)((ca ^ aS[1]) << 4));
                const uint32_t bsw = (uint32_t)((cb ^ bS) << 4);
                LDSM_X4(bb0[0], bb0[1], bb0[2], bb0[3], bBase + bsw);
                LDSM_X4(bb1[0], bb1[1], bb1[2], bb1[3], bBase + 4096u + bsw);

                MMA16816(acc[0][0], a0, bb0[0], bb0[1]);
                MMA16816(acc[0][1], a0, bb0[2], bb0[3]);
                MMA16816(acc[0][2], a0, bb1[0], bb1[1]);
                MMA16816(acc[0][3], a0, bb1[2], bb1[3]);
                MMA16816(acc[1][0], a1, bb0[0], bb0[1]);
                MMA16816(acc[1][1], a1, bb0[2], bb0[3]);
                MMA16816(acc[1][2], a1, bb1[0], bb1[1]);
                MMA16816(acc[1][3], a1, bb1[2], bb1[3]);
            }

            __syncthreads();   // all warps done reading buf (and, for k==2, Xs)
            if (tid == 0 && n + 2 < 24) {
                const int nk = (n + 2) % 3;
                MBAR_EXPECT_TX(ld_mb[buf], 32768u);
                BULK_G2S(sb + WS_OFF + (uint32_t)buf * 32768u,
                         (uint64_t)&g_Wh[nk * 16384], 32768u, ld_mb[buf]);
            }
        }

        // ---- epilogue: bias + ReLU + running segment max (registers) ----
        #pragma unroll
        for (int mt = 0; mt < 2; ++mt)
            #pragma unroll
            for (int nt = 0; nt < 4; ++nt)
                #pragma unroll
                for (int e = 0; e < 4; ++e) {
                    const int half = e >> 1;
                    const int idx = mt * 2 + half;
                    float v = acc[mt][nt][e] + biasv[idx];
                    v = fmaxf(v, 0.f);
                    const int l = pbase + wl * 32 + nt * 8 + colc + (e & 1);
                    if (l < m1hi)          rm[idx][0] = fmaxf(rm[idx][0], v);
                    if (l >= e1 && l < e2) rm[idx][1] = fmaxf(rm[idx][1], v);
                    if (l >= m3lo)         rm[idx][2] = fmaxf(rm[idx][2], v);
                }
    }

    // ---- reduce per-thread maxima -> pooled ----
    #pragma unroll
    for (int i = 0; i < 4; ++i) {
        const int f = wf * 32 + (i >> 1) * 16 + rowc + (i & 1) * 8;
        atomicMax(&pooled[f],            __float_as_uint(rm[i][0]));
        atomicMax(&pooled[FILT + f],     __float_as_uint(rm[i][1]));
        atomicMax(&pooled[2 * FILT + f], __float_as_uint(rm[i][2]));
    }
    __syncthreads();

    // ---- FC ----
    if (tid < NCLS) {
        float a = fc_b[tid];
        const float* wv = &fc_w[tid * 3 * FILT];
        #pragma unroll 8
        for (int i = 0; i < 3 * FILT; ++i)
            a = fmaf(__uint_as_float(pooled[i]), __ldg(&wv[i]), a);
        out[b * NCLS + tid] = a;
    }
}

extern "C" void kernel_launch(void* const* d_in, const int* in_sizes, int n_in,
                              void* d_out, int out_size) {
    const int*   char_ids = (const int*)  d_in[0];
    const int*   pos_e1   = (const int*)  d_in[1];
    const int*   pos_e2   = (const int*)  d_in[2];
    const float* emb      = (const float*)d_in[3];
    const float* conv_w   = (const float*)d_in[4];
    const float* conv_b   = (const float*)d_in[5];
    const float* fc_w     = (const float*)d_in[6];
    const float* fc_b     = (const float*)d_in[7];
    float* out = (float*)d_out;

    cudaFuncSetAttribute(pcnn_hmma_kernel,
                         cudaFuncAttributeMaxDynamicSharedMemorySize, SMEM_BYTES);

    prep_w_kernel<<<(KW * FILT * EMB + 255) / 256, 256>>>(conv_w);
    pcnn_hmma_kernel<<<BATCH, 256, SMEM_BYTES>>>(
        char_ids, pos_e1, pos_e2, emb, conv_b, fc_w, fc_b, out);
}

// round 10
// speedup vs baseline: 5.3618x; 1.0906x over previous
#include <cuda_runtime.h>
#include <cuda_fp16.h>
#include <cstdint>

#define BATCH 512
#define SEQ   512
#define EMB   128
#define FILT  128
#define KW    3
#define NCLS  53

// ---- smem layout (bytes) ----
#define WS_OFF   0                 // W fp16 [3][128 f][128 e], resident, chunk-swizzled
#define WS_BYTES 98304
#define XS_OFF   98304             // X fp16 [66 rows][128 e], row=256B, chunk-swizzled
#define XS_BYTES 16896
#define POOL_OFF XS_OFF            // overlay: pooled[3][128] reuses XS after last pass
#define MBAR_OFF 115200
#define SMEM_BYTES 115264          // x2 CTAs = 230528 <= 228KB carveout

// pre-swizzled fp16 weights, tap-major: g_Wh[k*16384 + f*128 + ((e>>3)^(f&7))*8 + (e&7)]
__device__ __align__(16) __half g_Wh[KW * FILT * EMB];

__device__ __forceinline__ uint32_t smem_u32(const void* p) {
    uint32_t a;
    asm("{ .reg .u64 t; cvta.to.shared.u64 t, %1; cvt.u32.u64 %0, t; }" : "=r"(a) : "l"(p));
    return a;
}

#define MBAR_INIT(a, c) asm volatile("mbarrier.init.shared.b64 [%0], %1;" :: "r"(a), "r"(c) : "memory")
#define MBAR_EXPECT_TX(a, n) asm volatile("mbarrier.arrive.expect_tx.shared.b64 _, [%0], %1;" :: "r"(a), "r"(n) : "memory")
#define MBAR_WAIT(a, p) do { \
    uint32_t _m = (a); uint32_t _p = (p); \
    asm volatile("{\n\t.reg .pred P;\n\tWL_%=:\n\t" \
        "mbarrier.try_wait.parity.acquire.cta.shared::cta.b64 P, [%0], %1, 0x989680;\n\t" \
        "@P bra.uni WD_%=;\n\tbra.uni WL_%=;\n\tWD_%=:\n\t}" :: "r"(_m), "r"(_p) : "memory"); \
} while (0)

#define BULK_G2S(dst, src, nbytes, mbar) \
    asm volatile("cp.async.bulk.shared::cluster.global.mbarrier::complete_tx::bytes [%0], [%1], %2, [%3];" \
        :: "r"(dst), "l"(src), "r"(nbytes), "r"(mbar) : "memory")

#define LDSM_X4(r0, r1, r2, r3, a) \
    asm volatile("ldmatrix.sync.aligned.m8n8.x4.shared.b16 {%0,%1,%2,%3}, [%4];" \
        : "=r"(r0), "=r"(r1), "=r"(r2), "=r"(r3) : "r"(a))

#define MMA16816(c, a, b0, b1) \
    asm volatile("mma.sync.aligned.m16n8k16.row.col.f32.f16.f16.f32 " \
        "{%0,%1,%2,%3}, {%4,%5,%6,%7}, {%8,%9}, {%0,%1,%2,%3};" \
        : "+f"((c)[0]), "+f"((c)[1]), "+f"((c)[2]), "+f"((c)[3]) \
        : "r"((a)[0]), "r"((a)[1]), "r"((a)[2]), "r"((a)[3]), "r"(b0), "r"(b1))

// ---------------- prep: convert + swizzle weights ----------------
__global__ void prep_w_kernel(const float* __restrict__ conv_w) {
    int idx = blockIdx.x * blockDim.x + threadIdx.x;
    if (idx >= KW * FILT * EMB) return;
    int k = idx / (FILT * EMB);
    int rem = idx - k * FILT * EMB;
    int f = rem >> 7, e = rem & 127;
    float w = conv_w[(f * EMB + e) * KW + k];
    int dst = k * 16384 + f * 128 + (((e >> 3) ^ (f & 7)) << 3) + (e & 7);
    g_Wh[dst] = __float2half_rn(w);
}

// ---------------- main kernel: one CTA per batch, 2 CTAs/SM ----------------
__global__ __launch_bounds__(256, 2)
void pcnn_hmma_kernel(const int*   __restrict__ char_ids,
                      const int*   __restrict__ pos_e1,
                      const int*   __restrict__ pos_e2,
                      const float* __restrict__ emb,
                      const float* __restrict__ conv_b,
                      const float* __restrict__ fc_w,
                      const float* __restrict__ fc_b,
                      float*       __restrict__ out)
{
    extern __shared__ char smem[];
    const uint32_t sb = smem_u32(smem);
    const int tid  = threadIdx.x;
    const int w    = tid >> 5;
    const int lane = tid & 31;
    const int b    = blockIdx.x;

    const int wf = w & 3;   // f-tile: f in [wf*32, wf*32+32)
    const int wl = w >> 2;  // l-tile within pass: l_local in [wl*32, wl*32+32)

    const uint32_t mbar = sb + MBAR_OFF;

    // kick off the single resident-W bulk copy (96 KB)
    if (tid == 0) {
        MBAR_INIT(mbar, 1);
        MBAR_EXPECT_TX(mbar, WS_BYTES);
        BULK_G2S(sb + WS_OFF, (uint64_t)&g_Wh[0], WS_BYTES, mbar);
    }

    // segment bounds
    const int p1 = pos_e1[b], p2 = pos_e2[b];
    int e1 = min(p1, p2), e2 = max(p1, p2);
    if (e1 == e2) e2 = min(e1 + 1, SEQ);
    const int m1hi = max(e1, 1);
    const int m3lo = min(e2, SEQ - 1);

    // per-thread epilogue constants
    const int rowc = lane >> 2;
    const int colc = (lane & 3) * 2;
    float biasv[4];
    #pragma unroll
    for (int i = 0; i < 4; ++i)
        biasv[i] = conv_b[wf * 32 + (i >> 1) * 16 + rowc + (i & 1) * 8];
    float rm[4][3];
    #pragma unroll
    for (int i = 0; i < 4; ++i) { rm[i][0] = 0.f; rm[i][1] = 0.f; rm[i][2] = 0.f; }

    // ldmatrix lane-address components
    const int a_row = lane & 15;          // A: row within 16
    const int a_cg  = lane >> 4;          // A: col-chunk
    const int b_r  = (lane & 7) + ((lane >> 4) << 3);  // B: n-row
    const int b_kc = (lane >> 3) & 1;                   // B: k-chunk

    bool w_waited = false;

    #pragma unroll 1
    for (int pass = 0; pass < 8; ++pass) {
        const int pbase = pass * 64;

        // ---- gather X tile (+halo) into Xs: rows p=0..65 (l = pbase+p-1) ----
        for (int v = tid; v < 66 * 16; v += 256) {
            const int p = v >> 4;
            const int c = v & 15;         // 16B chunk (8 e-values)
            const int l = pbase + p - 1;
            uint4 st = make_uint4(0u, 0u, 0u, 0u);
            if (l >= 0 && l < SEQ) {
                const int id = __ldg(&char_ids[b * SEQ + l]);
                const float4* src = (const float4*)(emb + (size_t)id * EMB) + c * 2;
                const float4 x0 = __ldg(src);
                const float4 x1 = __ldg(src + 1);
                __half2 h0 = __floats2half2_rn(x0.x, x0.y);
                __half2 h1 = __floats2half2_rn(x0.z, x0.w);
                __half2 h2 = __floats2half2_rn(x1.x, x1.y);
                __half2 h3 = __floats2half2_rn(x1.z, x1.w);
                st.x = *(uint32_t*)&h0; st.y = *(uint32_t*)&h1;
                st.z = *(uint32_t*)&h2; st.w = *(uint32_t*)&h3;
            }
            *(uint4*)(smem + XS_OFF + p * 256 + ((c ^ (p & 7)) << 4)) = st;
        }
        if (!w_waited) { MBAR_WAIT(mbar, 0u); w_waited = true; }
        __syncthreads();

        // ---- GEMM: C[32f x 32l] += sum_k sum_e W[k] * X(shifted by k) ----
        float acc[2][4][4];
        #pragma unroll
        for (int mt = 0; mt < 2; ++mt)
            #pragma unroll
            for (int nt = 0; nt < 4; ++nt)
                #pragma unroll
                for (int i = 0; i < 4; ++i) acc[mt][nt][i] = 0.f;

        #pragma unroll
        for (int k = 0; k < KW; ++k) {
            const uint32_t wsBase = sb + WS_OFF + (uint32_t)k * 32768u;
            uint32_t aBase[2]; int aS[2];
            #pragma unroll
            for (int mt = 0; mt < 2; ++mt) {
                const int f = wf * 32 + mt * 16 + a_row;
                aBase[mt] = wsBase + (uint32_t)f * 256u;
                aS[mt] = f & 7;
            }
            const int p0 = wl * 32 + b_r + k;
            const uint32_t bBase = sb + XS_OFF + (uint32_t)p0 * 256u;
            const int bS = p0 & 7;

            #pragma unroll
            for (int ec = 0; ec < 8; ++ec) {
                uint32_t a0[4], a1[4], bb0[4], bb1[4];
                const int ca = ec * 2 + a_cg;
                const int cb = ec * 2 + b_kc;
                LDSM_X4(a0[0], a0[1], a0[2], a0[3],
                        aBase[0] + (uint32_t)((ca ^ aS[0]) << 4));
                LDSM_X4(a1[0], a1[1], a1[2], a1[3],
                        aBase[1] + (uint32_t)((ca ^ aS[1]) << 4));
                const uint32_t bsw = (uint32_t)((cb ^ bS) << 4);
                LDSM_X4(bb0[0], bb0[1], bb0[2], bb0[3], bBase + bsw);
                LDSM_X4(bb1[0], bb1[1], bb1[2], bb1[3], bBase + 4096u + bsw);

                MMA16816(acc[0][0], a0, bb0[0], bb0[1]);
                MMA16816(acc[0][1], a0, bb0[2], bb0[3]);
                MMA16816(acc[0][2], a0, bb1[0], bb1[1]);
                MMA16816(acc[0][3], a0, bb1[2], bb1[3]);
                MMA16816(acc[1][0], a1, bb0[0], bb0[1]);
                MMA16816(acc[1][1], a1, bb0[2], bb0[3]);
                MMA16816(acc[1][2], a1, bb1[0], bb1[1]);
                MMA16816(acc[1][3], a1, bb1[2], bb1[3]);
            }
        }
        __syncthreads();   // all warps done reading Xs before next gather

        // ---- epilogue: bias + ReLU + running segment max (registers) ----
        #pragma unroll
        for (int mt = 0; mt < 2; ++mt)
            #pragma unroll
            for (int nt = 0; nt < 4; ++nt)
                #pragma unroll
                for (int e = 0; e < 4; ++e) {
                    const int half = e >> 1;
                    const int idx = mt * 2 + half;
                    float v = acc[mt][nt][e] + biasv[idx];
                    v = fmaxf(v, 0.f);
                    const int l = pbase + wl * 32 + nt * 8 + colc + (e & 1);
                    if (l < m1hi)          rm[idx][0] = fmaxf(rm[idx][0], v);
                    if (l >= e1 && l < e2) rm[idx][1] = fmaxf(rm[idx][1], v);
                    if (l >= m3lo)         rm[idx][2] = fmaxf(rm[idx][2], v);
                }
    }

    // ---- pooled overlays XS: init after last pass, then reduce ----
    unsigned* pooled = (unsigned*)(smem + POOL_OFF);
    for (int i = tid; i < 3 * FILT; i += 256) pooled[i] = 0u;
    __syncthreads();

    #pragma unroll
    for (int i = 0; i < 4; ++i) {
        const int f = wf * 32 + (i >> 1) * 16 + rowc + (i & 1) * 8;
        atomicMax(&pooled[f],            __float_as_uint(rm[i][0]));
        atomicMax(&pooled[FILT + f],     __float_as_uint(rm[i][1]));
        atomicMax(&pooled[2 * FILT + f], __float_as_uint(rm[i][2]));
    }
    __syncthreads();

    // ---- FC ----
    if (tid < NCLS) {
        float a = fc_b[tid];
        const float* wv = &fc_w[tid * 3 * FILT];
        #pragma unroll 8
        for (int i = 0; i < 3 * FILT; ++i)
            a = fmaf(__uint_as_float(pooled[i]), __ldg(&wv[i]), a);
        out[b * NCLS + tid] = a;
    }
}

extern "C" void kernel_launch(void* const* d_in, const int* in_sizes, int n_in,
                              void* d_out, int out_size) {
    const int*   char_ids = (const int*)  d_in[0];
    const int*   pos_e1   = (const int*)  d_in[1];
    const int*   pos_e2   = (const int*)  d_in[2];
    const float* emb      = (const float*)d_in[3];
    const float* conv_w   = (const float*)d_in[4];
    const float* conv_b   = (const float*)d_in[5];
    const float* fc_w     = (const float*)d_in[6];
    const float* fc_b     = (const float*)d_in[7];
    float* out = (float*)d_out;

    cudaFuncSetAttribute(pcnn_hmma_kernel,
                         cudaFuncAttributeMaxDynamicSharedMemorySize, SMEM_BYTES);

    prep_w_kernel<<<(KW * FILT * EMB + 255) / 256, 256>>>(conv_w);
    pcnn_hmma_kernel<<<BATCH, 256, SMEM_BYTES>>>(
        char_ids, pos_e1, pos_e2, emb, conv_b, fc_w, fc_b, out);
}

// round 11
// speedup vs baseline: 5.7004x; 1.0631x over previous
#include <cuda_runtime.h>
#include <cuda_fp16.h>
#include <cstdint>

#define BATCH 512
#define SEQ   512
#define EMB   128
#define FILT  128
#define KW    3
#define NCLS  53
#define VOCAB 21128

// ---- smem layout (bytes) ----
#define WS_OFF   0                 // W fp16 [3][128 f][128 e], resident, chunk-swizzled
#define WS_BYTES 98304
#define XS_BYTES 16896             // one X buffer: 66 rows x 256B
#define XS_OFF(g, d) (WS_BYTES + ((g) * 2 + (d)) * XS_BYTES)   // 4 buffers
#define POOL_OFF(g)  (165888 + (g) * 1536)                      // uint [3][128] per group
#define MBAR_OFF 168960
#define SMEM_BYTES 169024          // 1 CTA/SM

// pre-swizzled fp16 weights: g_Wh[k*16384 + f*128 + ((e>>3)^(f&7))*8 + (e&7)]
__device__ __align__(16) __half g_Wh[KW * FILT * EMB];
// fp16 embedding table (row-major, 256B rows)
__device__ __align__(16) __half g_EmbH[VOCAB * EMB];

__device__ __forceinline__ uint32_t smem_u32(const void* p) {
    uint32_t a;
    asm("{ .reg .u64 t; cvta.to.shared.u64 t, %1; cvt.u32.u64 %0, t; }" : "=r"(a) : "l"(p));
    return a;
}

#define MBAR_INIT(a, c) asm volatile("mbarrier.init.shared.b64 [%0], %1;" :: "r"(a), "r"(c) : "memory")
#define MBAR_EXPECT_TX(a, n) asm volatile("mbarrier.arrive.expect_tx.shared.b64 _, [%0], %1;" :: "r"(a), "r"(n) : "memory")
#define MBAR_WAIT(a, p) do { \
    uint32_t _m = (a); uint32_t _p = (p); \
    asm volatile("{\n\t.reg .pred P;\n\tWL_%=:\n\t" \
        "mbarrier.try_wait.parity.acquire.cta.shared::cta.b64 P, [%0], %1, 0x989680;\n\t" \
        "@P bra.uni WD_%=;\n\tbra.uni WL_%=;\n\tWD_%=:\n\t}" :: "r"(_m), "r"(_p) : "memory"); \
} while (0)

#define BULK_G2S(dst, src, nbytes, mbar) \
    asm volatile("cp.async.bulk.shared::cluster.global.mbarrier::complete_tx::bytes [%0], [%1], %2, [%3];" \
        :: "r"(dst), "l"(src), "r"(nbytes), "r"(mbar) : "memory")

#define CP_ASYNC16(dst, src, srcsz) \
    asm volatile("cp.async.ca.shared.global [%0], [%1], 16, %2;" \
        :: "r"(dst), "l"(src), "r"(srcsz) : "memory")
#define CP_COMMIT() asm volatile("cp.async.commit_group;" ::: "memory")
#define CP_WAIT0()  asm volatile("cp.async.wait_group 0;" ::: "memory")

#define GBAR(g) asm volatile("bar.sync %0, 256;" :: "r"((g) + 1) : "memory")

#define LDSM_X4(r0, r1, r2, r3, a) \
    asm volatile("ldmatrix.sync.aligned.m8n8.x4.shared.b16 {%0,%1,%2,%3}, [%4];" \
        : "=r"(r0), "=r"(r1), "=r"(r2), "=r"(r3) : "r"(a))

#define MMA16816(c, a, b0, b1) \
    asm volatile("mma.sync.aligned.m16n8k16.row.col.f32.f16.f16.f32 " \
        "{%0,%1,%2,%3}, {%4,%5,%6,%7}, {%8,%9}, {%0,%1,%2,%3};" \
        : "+f"((c)[0]), "+f"((c)[1]), "+f"((c)[2]), "+f"((c)[3]) \
        : "r"((a)[0]), "r"((a)[1]), "r"((a)[2]), "r"((a)[3]), "r"(b0), "r"(b1))

// ---------------- prep kernels ----------------
__global__ void prep_w_kernel(const float* __restrict__ conv_w) {
    int idx = blockIdx.x * blockDim.x + threadIdx.x;
    if (idx >= KW * FILT * EMB) return;
    int k = idx / (FILT * EMB);
    int rem = idx - k * FILT * EMB;
    int f = rem >> 7, e = rem & 127;
    float w = conv_w[(f * EMB + e) * KW + k];
    int dst = k * 16384 + f * 128 + (((e >> 3) ^ (f & 7)) << 3) + (e & 7);
    g_Wh[dst] = __float2half_rn(w);
}

__global__ void prep_emb_kernel(const float* __restrict__ emb) {
    int idx = blockIdx.x * blockDim.x + threadIdx.x;   // one float4 per thread
    if (idx >= VOCAB * EMB / 4) return;
    const float4 x = __ldg((const float4*)emb + idx);
    __half2 h0 = __floats2half2_rn(x.x, x.y);
    __half2 h1 = __floats2half2_rn(x.z, x.w);
    uint2 st;
    st.x = *(uint32_t*)&h0; st.y = *(uint32_t*)&h1;
    *((uint2*)g_EmbH + idx) = st;
}

// ---------------- main kernel: 512 thr = 2 groups, 2 batches/CTA ----------------
__global__ __launch_bounds__(512, 1)
void pcnn_hmma_kernel(const int*   __restrict__ char_ids,
                      const int*   __restrict__ pos_e1,
                      const int*   __restrict__ pos_e2,
                      const float* __restrict__ conv_b,
                      const float* __restrict__ fc_w,
                      const float* __restrict__ fc_b,
                      float*       __restrict__ out)
{
    extern __shared__ char smem[];
    const uint32_t sb = smem_u32(smem);
    const int tid  = threadIdx.x;
    const int g    = tid >> 8;          // group 0/1
    const int gtid = tid & 255;
    const int w    = gtid >> 5;
    const int lane = tid & 31;
    const int b    = blockIdx.x * 2 + g;

    const int wf = w & 3;   // f-tile
    const int wl = w >> 2;  // l-tile within pass

    const uint32_t mbar = sb + MBAR_OFF;

    // resident W copy (96 KB, once per CTA)
    if (tid == 0) {
        MBAR_INIT(mbar, 1);
        MBAR_EXPECT_TX(mbar, WS_BYTES);
        BULK_G2S(sb + WS_OFF, (uint64_t)&g_Wh[0], WS_BYTES, mbar);
    }
    __syncthreads();   // mbar visible to all before any wait

    // segment bounds
    const int p1 = pos_e1[b], p2 = pos_e2[b];
    int e1 = min(p1, p2), e2 = max(p1, p2);
    if (e1 == e2) e2 = min(e1 + 1, SEQ);
    const int m1hi = max(e1, 1);
    const int m3lo = min(e2, SEQ - 1);

    // epilogue constants
    const int rowc = lane >> 2;
    const int colc = (lane & 3) * 2;
    float biasv[4];
    #pragma unroll
    for (int i = 0; i < 4; ++i)
        biasv[i] = conv_b[wf * 32 + (i >> 1) * 16 + rowc + (i & 1) * 8];
    float rm[4][3];
    #pragma unroll
    for (int i = 0; i < 4; ++i) { rm[i][0] = 0.f; rm[i][1] = 0.f; rm[i][2] = 0.f; }

    // ldmatrix lane-address components
    const int a_row = lane & 15;
    const int a_cg  = lane >> 4;
    const int b_r  = (lane & 7) + ((lane >> 4) << 3);
    const int b_kc = (lane >> 3) & 1;

    unsigned* pooled = (unsigned*)(smem + POOL_OFF(g));
    for (int i = gtid; i < 3 * FILT; i += 256) pooled[i] = 0u;

    const uint32_t xsb[2] = {sb + (uint32_t)XS_OFF(g, 0), sb + (uint32_t)XS_OFF(g, 1)};

    // ---- async gather of one X tile into buffer d (cp.async, zero-filled halo) ----
    #define ISSUE_GATHER(pass, d) do { \
        const int _pb = (pass) * 64; \
        _Pragma("unroll") \
        for (int it = 0; it < 5; ++it) { \
            const int v = gtid + it * 256; \
            if (v < 66 * 16) { \
                const int p = v >> 4, c = v & 15; \
                const int l = _pb + p - 1; \
                const int valid = (l >= 0 && l < SEQ); \
                const int lc = valid ? l : 0; \
                const int id = __ldg(&char_ids[b * SEQ + lc]); \
                const uint64_t src = (uint64_t)&g_EmbH[(size_t)id * EMB] + (uint32_t)(c << 4); \
                const uint32_t dst = xsb[d] + (uint32_t)(p * 256 + ((c ^ (p & 7)) << 4)); \
                CP_ASYNC16(dst, src, valid ? 16 : 0); \
            } \
        } \
        CP_COMMIT(); \
    } while (0)

    // prologue: fill buffer 0, wait W + gather
    ISSUE_GATHER(0, 0);
    CP_WAIT0();
    MBAR_WAIT(mbar, 0u);
    GBAR(g);

    int buf = 0;
    #pragma unroll 1
    for (int pass = 0; pass < 8; ++pass) {
        const int pbase = pass * 64;

        // prefetch next tile into the other buffer (overlapped with GEMM)
        if (pass < 7) ISSUE_GATHER(pass + 1, buf ^ 1);

        // ---- GEMM: C[32f x 32l] += sum_k sum_e W[k] * X(shifted by k) ----
        float acc[2][4][4];
        #pragma unroll
        for (int mt = 0; mt < 2; ++mt)
            #pragma unroll
            for (int nt = 0; nt < 4; ++nt)
                #pragma unroll
                for (int i = 0; i < 4; ++i) acc[mt][nt][i] = 0.f;

        #pragma unroll
        for (int k = 0; k < KW; ++k) {
            const uint32_t wsBase = sb + WS_OFF + (uint32_t)k * 32768u;
            uint32_t aBase[2]; int aS[2];
            #pragma unroll
            for (int mt = 0; mt < 2; ++mt) {
                const int f = wf * 32 + mt * 16 + a_row;
                aBase[mt] = wsBase + (uint32_t)f * 256u;
                aS[mt] = f & 7;
            }
            const int p0 = wl * 32 + b_r + k;
            const uint32_t bBase = xsb[buf] + (uint32_t)p0 * 256u;
            const int bS = p0 & 7;

            #pragma unroll
            for (int ec = 0; ec < 8; ++ec) {
                uint32_t a0[4], a1[4], bb0[4], bb1[4];
                const int ca = ec * 2 + a_cg;
                const int cb = ec * 2 + b_kc;
                LDSM_X4(a0[0], a0[1], a0[2], a0[3],
                        aBase[0] + (uint32_t)((ca ^ aS[0]) << 4));
                LDSM_X4(a1[0], a1[1], a1[2], a1[3],
                        aBase[1] + (uint32_t)((ca ^ aS[1]) << 4));
                const uint32_t bsw = (uint32_t)((cb ^ bS) << 4);
                LDSM_X4(bb0[0], bb0[1], bb0[2], bb0[3], bBase + bsw);
                LDSM_X4(bb1[0], bb1[1], bb1[2], bb1[3], bBase + 4096u + bsw);

                MMA16816(acc[0][0], a0, bb0[0], bb0[1]);
                MMA16816(acc[0][1], a0, bb0[2], bb0[3]);
                MMA16816(acc[0][2], a0, bb1[0], bb1[1]);
                MMA16816(acc[0][3], a0, bb1[2], bb1[3]);
                MMA16816(acc[1][0], a1, bb0[0], bb0[1]);
                MMA16816(acc[1][1], a1, bb0[2], bb0[3]);
                MMA16816(acc[1][2], a1, bb1[0], bb1[1]);
                MMA16816(acc[1][3], a1, bb1[2], bb1[3]);
            }
        }

        // ---- epilogue: bias + ReLU + running segment max ----
        #pragma unroll
        for (int mt = 0; mt < 2; ++mt)
            #pragma unroll
            for (int nt = 0; nt < 4; ++nt)
                #pragma unroll
                for (int e = 0; e < 4; ++e) {
                    const int half = e >> 1;
                    const int idx = mt * 2 + half;
                    float v = acc[mt][nt][e] + biasv[idx];
                    v = fmaxf(v, 0.f);
                    const int l = pbase + wl * 32 + nt * 8 + colc + (e & 1);
                    if (l < m1hi)          rm[idx][0] = fmaxf(rm[idx][0], v);
                    if (l >= e1 && l < e2) rm[idx][1] = fmaxf(rm[idx][1], v);
                    if (l >= m3lo)         rm[idx][2] = fmaxf(rm[idx][2], v);
                }

        if (pass < 7) CP_WAIT0();   // next buffer landed
        GBAR(g);                    // group done reading buf; cp.async stores visible
        buf ^= 1;
    }

    // ---- reduce per-thread maxima -> pooled (per group) ----
    #pragma unroll
    for (int i = 0; i < 4; ++i) {
        const int f = wf * 32 + (i >> 1) * 16 + rowc + (i & 1) * 8;
        atomicMax(&pooled[f],            __float_as_uint(rm[i][0]));
        atomicMax(&pooled[FILT + f],     __float_as_uint(rm[i][1]));
        atomicMax(&pooled[2 * FILT + f], __float_as_uint(rm[i][2]));
    }
    GBAR(g);

    // ---- FC ----
    if (gtid < NCLS) {
        float a = fc_b[gtid];
        const float* wv = &fc_w[gtid * 3 * FILT];
        #pragma unroll 8
        for (int i = 0; i < 3 * FILT; ++i)
            a = fmaf(__uint_as_float(pooled[i]), __ldg(&wv[i]), a);
        out[b * NCLS + gtid] = a;
    }
}

extern "C" void kernel_launch(void* const* d_in, const int* in_sizes, int n_in,
                              void* d_out, int out_size) {
    const int*   char_ids = (const int*)  d_in[0];
    const int*   pos_e1   = (const int*)  d_in[1];
    const int*   pos_e2   = (const int*)  d_in[2];
    const float* emb      = (const float*)d_in[3];
    const float* conv_w   = (const float*)d_in[4];
    const float* conv_b   = (const float*)d_in[5];
    const float* fc_w     = (const float*)d_in[6];
    const float* fc_b     = (const float*)d_in[7];
    float* out = (float*)d_out;

    cudaFuncSetAttribute(pcnn_hmma_kernel,
                         cudaFuncAttributeMaxDynamicSharedMemorySize, SMEM_BYTES);

    prep_w_kernel<<<(KW * FILT * EMB + 255) / 256, 256>>>(conv_w);
    prep_emb_kernel<<<(VOCAB * EMB / 4 + 255) / 256, 256>>>(emb);
    pcnn_hmma_kernel<<<BATCH / 2, 512, SMEM_BYTES>>>(
        char_ids, pos_e1, pos_e2, conv_b, fc_w, fc_b, out);
}

// round 12
// speedup vs baseline: 6.0650x; 1.0640x over previous
#include <cuda_runtime.h>
#include <cuda_fp16.h>
#include <cstdint>

#define BATCH 512
#define SEQ   512
#define EMB   128
#define FILT  128
#define KW    3
#define NCLS  53
#define VOCAB 21128
#define NUNITS (BATCH * 4)        // quarter-batch units, 2 passes of 64 each

// ---- smem layout (bytes) ----
#define WS_OFF   0                 // W fp16 [3][128 f][128 e], resident, chunk-swizzled
#define WS_BYTES 98304
#define XS_BYTES 16896             // one X buffer: 66 rows x 256B
#define XS_OFF(g, d) (WS_BYTES + ((g) * 2 + (d)) * XS_BYTES)   // 4 buffers
#define MBAR_OFF 165888
#define SMEM_BYTES 165952          // 1 CTA/SM

// pre-swizzled fp16 weights: g_Wh[k*16384 + f*128 + ((e>>3)^(f&7))*8 + (e&7)]
__device__ __align__(16) __half g_Wh[KW * FILT * EMB];
// fp16 embedding table (row-major, 256B rows)
__device__ __align__(16) __half g_EmbH[VOCAB * EMB];
// global segment-max pool: [batch][3][128] as float bits (zeroed in prep)
__device__ __align__(16) unsigned g_Pool[BATCH * 3 * FILT];

__device__ __forceinline__ uint32_t smem_u32(const void* p) {
    uint32_t a;
    asm("{ .reg .u64 t; cvta.to.shared.u64 t, %1; cvt.u32.u64 %0, t; }" : "=r"(a) : "l"(p));
    return a;
}

#define MBAR_INIT(a, c) asm volatile("mbarrier.init.shared.b64 [%0], %1;" :: "r"(a), "r"(c) : "memory")
#define MBAR_EXPECT_TX(a, n) asm volatile("mbarrier.arrive.expect_tx.shared.b64 _, [%0], %1;" :: "r"(a), "r"(n) : "memory")
#define MBAR_WAIT(a, p) do { \
    uint32_t _m = (a); uint32_t _p = (p); \
    asm volatile("{\n\t.reg .pred P;\n\tWL_%=:\n\t" \
        "mbarrier.try_wait.parity.acquire.cta.shared::cta.b64 P, [%0], %1, 0x989680;\n\t" \
        "@P bra.uni WD_%=;\n\tbra.uni WL_%=;\n\tWD_%=:\n\t}" :: "r"(_m), "r"(_p) : "memory"); \
} while (0)

#define BULK_G2S(dst, src, nbytes, mbar) \
    asm volatile("cp.async.bulk.shared::cluster.global.mbarrier::complete_tx::bytes [%0], [%1], %2, [%3];" \
        :: "r"(dst), "l"(src), "r"(nbytes), "r"(mbar) : "memory")

#define CP_ASYNC16(dst, src, srcsz) \
    asm volatile("cp.async.ca.shared.global [%0], [%1], 16, %2;" \
        :: "r"(dst), "l"(src), "r"(srcsz) : "memory")
#define CP_COMMIT() asm volatile("cp.async.commit_group;" ::: "memory")
#define CP_WAIT0()  asm volatile("cp.async.wait_group 0;" ::: "memory")

#define GBAR(g) asm volatile("bar.sync %0, 256;" :: "r"((g) + 1) : "memory")

#define LDSM_X4(r0, r1, r2, r3, a) \
    asm volatile("ldmatrix.sync.aligned.m8n8.x4.shared.b16 {%0,%1,%2,%3}, [%4];" \
        : "=r"(r0), "=r"(r1), "=r"(r2), "=r"(r3) : "r"(a))

#define MMA16816(c, a, b0, b1) \
    asm volatile("mma.sync.aligned.m16n8k16.row.col.f32.f16.f16.f32 " \
        "{%0,%1,%2,%3}, {%4,%5,%6,%7}, {%8,%9}, {%0,%1,%2,%3};" \
        : "+f"((c)[0]), "+f"((c)[1]), "+f"((c)[2]), "+f"((c)[3]) \
        : "r"((a)[0]), "r"((a)[1]), "r"((a)[2]), "r"((a)[3]), "r"(b0), "r"(b1))

// ---------------- combined prep: W swizzle + emb fp16 + pool zero ----------------
__global__ void prep_kernel(const float* __restrict__ conv_w,
                            const float* __restrict__ emb) {
    int idx = blockIdx.x * blockDim.x + threadIdx.x;
    if (idx < KW * FILT * EMB) {       // 49152: weight convert+swizzle
        int k = idx / (FILT * EMB);
        int rem = idx - k * FILT * EMB;
        int f = rem >> 7, e = rem & 127;
        float w = conv_w[(f * EMB + e) * KW + k];
        int dst = k * 16384 + f * 128 + (((e >> 3) ^ (f & 7)) << 3) + (e & 7);
        g_Wh[dst] = __float2half_rn(w);
        // 49152 uint4 = 512*384 uints: zero the pool
        ((uint4*)g_Pool)[idx] = make_uint4(0u, 0u, 0u, 0u);
    }
    if (idx < VOCAB * EMB / 4) {       // 676096: emb fp32 -> fp16
        const float4 x = __ldg((const float4*)emb + idx);
        __half2 h0 = __floats2half2_rn(x.x, x.y);
        __half2 h1 = __floats2half2_rn(x.z, x.w);
        uint2 st;
        st.x = *(uint32_t*)&h0; st.y = *(uint32_t*)&h1;
        *((uint2*)g_EmbH + idx) = st;
    }
}

// ---------------- main kernel: persistent, 2 groups/CTA, unit = quarter batch ----------------
__global__ __launch_bounds__(512, 1)
void pcnn_hmma_kernel(const int* __restrict__ char_ids,
                      const int* __restrict__ pos_e1,
                      const int* __restrict__ pos_e2,
                      const float* __restrict__ conv_b)
{
    extern __shared__ char smem[];
    const uint32_t sb = smem_u32(smem);
    const int tid  = threadIdx.x;
    const int g    = tid >> 8;          // group 0/1
    const int gtid = tid & 255;
    const int w    = gtid >> 5;
    const int lane = tid & 31;

    const int wf = w & 3;   // f-tile
    const int wl = w >> 2;  // l-tile within pass

    const uint32_t mbar = sb + MBAR_OFF;

    // resident W copy (96 KB, once per CTA for the whole kernel)
    if (tid == 0) {
        MBAR_INIT(mbar, 1);
        MBAR_EXPECT_TX(mbar, WS_BYTES);
        BULK_G2S(sb + WS_OFF, (uint64_t)&g_Wh[0], WS_BYTES, mbar);
    }
    __syncthreads();

    // epilogue constants (batch-independent)
    const int rowc = lane >> 2;
    const int colc = (lane & 3) * 2;
    float biasv[4];
    #pragma unroll
    for (int i = 0; i < 4; ++i)
        biasv[i] = conv_b[wf * 32 + (i >> 1) * 16 + rowc + (i & 1) * 8];
    float rm[4][3];
    #pragma unroll
    for (int i = 0; i < 4; ++i) { rm[i][0] = 0.f; rm[i][1] = 0.f; rm[i][2] = 0.f; }

    // ldmatrix lane-address components
    const int a_row = lane & 15;
    const int a_cg  = lane >> 4;
    const int b_r  = (lane & 7) + ((lane >> 4) << 3);
    const int b_kc = (lane >> 3) & 1;

    const uint32_t xsb[2] = {sb + (uint32_t)XS_OFF(g, 0), sb + (uint32_t)XS_OFF(g, 1)};

    // async gather of tile (batch bb, l-base pb) into buffer d
    #define ISSUE_GATHER(bb, pb, d) do { \
        _Pragma("unroll") \
        for (int it = 0; it < 5; ++it) { \
            const int v = gtid + it * 256; \
            if (v < 66 * 16) { \
                const int p = v >> 4, c = v & 15; \
                const int l = (pb) + p - 1; \
                const int valid = (l >= 0 && l < SEQ); \
                const int lc = valid ? l : 0; \
                const int id = __ldg(&char_ids[(bb) * SEQ + lc]); \
                const uint64_t src = (uint64_t)&g_EmbH[(size_t)id * EMB] + (uint32_t)(c << 4); \
                const uint32_t dst = xsb[d] + (uint32_t)(p * 256 + ((c ^ (p & 7)) << 4)); \
                CP_ASYNC16(dst, src, valid ? 16 : 0); \
            } \
        } \
        CP_COMMIT(); \
    } while (0)

    // static schedule: group slot s handles units s, s+nslots, ...; 2 passes/unit
    const int nslots = (int)gridDim.x * 2;
    const int slot = blockIdx.x * 2 + g;

    int cu = slot, cj = 0;
    bool valid = (cu < NUNITS);
    if (valid) ISSUE_GATHER(cu >> 2, (cu & 3) * 128, 0);
    CP_WAIT0();
    MBAR_WAIT(mbar, 0u);
    GBAR(g);

    int buf = 0;
    while (valid) {
        const int batch = cu >> 2;
        const int pbase = (cu & 3) * 128 + cj * 64;

        // segment bounds for this batch
        const int p1 = __ldg(&pos_e1[batch]), p2 = __ldg(&pos_e2[batch]);
        int e1 = min(p1, p2), e2 = max(p1, p2);
        if (e1 == e2) e2 = min(e1 + 1, SEQ);
        const int m1hi = max(e1, 1);
        const int m3lo = min(e2, SEQ - 1);

        // next pass in schedule
        int nu = cu, nj = cj + 1;
        if (nj == 2) { nu = cu + nslots; nj = 0; }
        const bool nvalid = (nu < NUNITS);
        if (nvalid) ISSUE_GATHER(nu >> 2, (nu & 3) * 128 + nj * 64, buf ^ 1);

        // ---- GEMM: C[32f x 32l] += sum_k sum_e W[k] * X(shifted by k) ----
        float acc[2][4][4];
        #pragma unroll
        for (int mt = 0; mt < 2; ++mt)
            #pragma unroll
            for (int nt = 0; nt < 4; ++nt)
                #pragma unroll
                for (int i = 0; i < 4; ++i) acc[mt][nt][i] = 0.f;

        #pragma unroll
        for (int k = 0; k < KW; ++k) {
            const uint32_t wsBase = sb + WS_OFF + (uint32_t)k * 32768u;
            uint32_t aBase[2]; int aS[2];
            #pragma unroll
            for (int mt = 0; mt < 2; ++mt) {
                const int f = wf * 32 + mt * 16 + a_row;
                aBase[mt] = wsBase + (uint32_t)f * 256u;
                aS[mt] = f & 7;
            }
            const int p0 = wl * 32 + b_r + k;
            const uint32_t bBase = xsb[buf] + (uint32_t)p0 * 256u;
            const int bS = p0 & 7;

            #pragma unroll
            for (int ec = 0; ec < 8; ++ec) {
                uint32_t a0[4], a1[4], bb0[4], bb1[4];
                const int ca = ec * 2 + a_cg;
                const int cb = ec * 2 + b_kc;
                LDSM_X4(a0[0], a0[1], a0[2], a0[3],
                        aBase[0] + (uint32_t)((ca ^ aS[0]) << 4));
                LDSM_X4(a1[0], a1[1], a1[2], a1[3],
                        aBase[1] + (uint32_t)((ca ^ aS[1]) << 4));
                const uint32_t bsw = (uint32_t)((cb ^ bS) << 4);
                LDSM_X4(bb0[0], bb0[1], bb0[2], bb0[3], bBase + bsw);
                LDSM_X4(bb1[0], bb1[1], bb1[2], bb1[3], bBase + 4096u + bsw);

                MMA16816(acc[0][0], a0, bb0[0], bb0[1]);
                MMA16816(acc[0][1], a0, bb0[2], bb0[3]);
                MMA16816(acc[0][2], a0, bb1[0], bb1[1]);
                MMA16816(acc[0][3], a0, bb1[2], bb1[3]);
                MMA16816(acc[1][0], a1, bb0[0], bb0[1]);
                MMA16816(acc[1][1], a1, bb0[2], bb0[3]);
                MMA16816(acc[1][2], a1, bb1[0], bb1[1]);
                MMA16816(acc[1][3], a1, bb1[2], bb1[3]);
            }
        }

        // ---- epilogue: bias + ReLU + running segment max ----
        #pragma unroll
        for (int mt = 0; mt < 2; ++mt)
            #pragma unroll
            for (int nt = 0; nt < 4; ++nt)
                #pragma unroll
                for (int e = 0; e < 4; ++e) {
                    const int half = e >> 1;
                    const int idx = mt * 2 + half;
                    float v = acc[mt][nt][e] + biasv[idx];
                    v = fmaxf(v, 0.f);
                    const int l = pbase + wl * 32 + nt * 8 + colc + (e & 1);
                    if (l < m1hi)          rm[idx][0] = fmaxf(rm[idx][0], v);
                    if (l >= e1 && l < e2) rm[idx][1] = fmaxf(rm[idx][1], v);
                    if (l >= m3lo)         rm[idx][2] = fmaxf(rm[idx][2], v);
                }

        // ---- unit end: flush register maxima to global pool (REDG, skip zeros) ----
        if (cj == 1) {
            unsigned* pb_ = &g_Pool[batch * 3 * FILT];
            #pragma unroll
            for (int i = 0; i < 4; ++i) {
                const int f = wf * 32 + (i >> 1) * 16 + rowc + (i & 1) * 8;
                if (rm[i][0] > 0.f) atomicMax(&pb_[f],            __float_as_uint(rm[i][0]));
                if (rm[i][1] > 0.f) atomicMax(&pb_[FILT + f],     __float_as_uint(rm[i][1]));
                if (rm[i][2] > 0.f) atomicMax(&pb_[2 * FILT + f], __float_as_uint(rm[i][2]));
                rm[i][0] = 0.f; rm[i][1] = 0.f; rm[i][2] = 0.f;
            }
        }

        CP_WAIT0();   // next buffer landed
        GBAR(g);      // group done reading buf; cp.async stores visible
        buf ^= 1;
        cu = nu; cj = nj; valid = nvalid;
    }
}

// ---------------- FC kernel: out[b][c] = pooled . fc_w[c] + fc_b[c] ----------------
__global__ __launch_bounds__(64, 8)
void fc_kernel(const float* __restrict__ fc_w,
               const float* __restrict__ fc_b,
               float* __restrict__ out) {
    const int b = blockIdx.x;
    const int c = threadIdx.x;
    if (c < NCLS) {
        float a = fc_b[c];
        const unsigned* pp = &g_Pool[b * 3 * FILT];
        const float* wv = &fc_w[c * 3 * FILT];
        #pragma unroll 8
        for (int i = 0; i < 3 * FILT; ++i)
            a = fmaf(__uint_as_float(pp[i]), __ldg(&wv[i]), a);
        out[b * NCLS + c] = a;
    }
}

extern "C" void kernel_launch(void* const* d_in, const int* in_sizes, int n_in,
                              void* d_out, int out_size) {
    const int*   char_ids = (const int*)  d_in[0];
    const int*   pos_e1   = (const int*)  d_in[1];
    const int*   pos_e2   = (const int*)  d_in[2];
    const float* emb      = (const float*)d_in[3];
    const float* conv_w   = (const float*)d_in[4];
    const float* conv_b   = (const float*)d_in[5];
    const float* fc_w     = (const float*)d_in[6];
    const float* fc_b     = (const float*)d_in[7];
    float* out = (float*)d_out;

    cudaFuncSetAttribute(pcnn_hmma_kernel,
                         cudaFuncAttributeMaxDynamicSharedMemorySize, SMEM_BYTES);

    prep_kernel<<<(VOCAB * EMB / 4 + 255) / 256, 256>>>(conv_w, emb);
    pcnn_hmma_kernel<<<152, 512, SMEM_BYTES>>>(char_ids, pos_e1, pos_e2, conv_b);
    fc_kernel<<<BATCH, 64>>>(fc_w, fc_b, out);
}

// round 15
// speedup vs baseline: 6.2802x; 1.0355x over previous
#include <cuda_runtime.h>
#include <cuda_fp16.h>
#include <cstdint>

#define BATCH 512
#define SEQ   512
#define EMB   128
#define FILT  128
#define KW    3
#define NCLS  53
#define VOCAB 21128
#define NUNITS (BATCH * 4)        // unit = quarter batch = one 128-l pass

// ---- smem layout (bytes) ----
#define WS_OFF   0                 // W fp16 [3][128 f][128 e], resident, chunk-swizzled
#define WS_BYTES 98304
#define XS_BYTES 33280             // one X buffer: 130 rows x 256B
#define XS_OFF(g, d) (WS_BYTES + ((g) * 2 + (d)) * XS_BYTES)   // 4 buffers
#define MBAR_OFF 231424
#define SMEM_BYTES 231488          // <= 232448 (227KB opt-in), 1 CTA/SM

// pre-swizzled fp16 weights: g_Wh[k*16384 + f*128 + ((e>>3)^(f&7))*8 + (e&7)]
__device__ __align__(16) __half g_Wh[KW * FILT * EMB];
// fp16 embedding table (row-major, 256B rows)
__device__ __align__(16) __half g_EmbH[VOCAB * EMB];
// global segment-max pool: [batch][3][128] as float bits (zeroed in prep)
__device__ __align__(16) unsigned g_Pool[BATCH * 3 * FILT];

__device__ __forceinline__ uint32_t smem_u32(const void* p) {
    uint32_t a;
    asm("{ .reg .u64 t; cvta.to.shared.u64 t, %1; cvt.u32.u64 %0, t; }" : "=r"(a) : "l"(p));
    return a;
}

#define MBAR_INIT(a, c) asm volatile("mbarrier.init.shared.b64 [%0], %1;" :: "r"(a), "r"(c) : "memory")
#define MBAR_EXPECT_TX(a, n) asm volatile("mbarrier.arrive.expect_tx.shared.b64 _, [%0], %1;" :: "r"(a), "r"(n) : "memory")
#define MBAR_WAIT(a, p) do { \
    uint32_t _m = (a); uint32_t _p = (p); \
    asm volatile("{\n\t.reg .pred P;\n\tWL_%=:\n\t" \
        "mbarrier.try_wait.parity.acquire.cta.shared::cta.b64 P, [%0], %1, 0x989680;\n\t" \
        "@P bra.uni WD_%=;\n\tbra.uni WL_%=;\n\tWD_%=:\n\t}" :: "r"(_m), "r"(_p) : "memory"); \
} while (0)

#define BULK_G2S(dst, src, nbytes, mbar) \
    asm volatile("cp.async.bulk.shared::cluster.global.mbarrier::complete_tx::bytes [%0], [%1], %2, [%3];" \
        :: "r"(dst), "l"(src), "r"(nbytes), "r"(mbar) : "memory")

#define CP_ASYNC16(dst, src, srcsz) \
    asm volatile("cp.async.ca.shared.global [%0], [%1], 16, %2;" \
        :: "r"(dst), "l"(src), "r"(srcsz) : "memory")
#define CP_COMMIT() asm volatile("cp.async.commit_group;" ::: "memory")
#define CP_WAIT0()  asm volatile("cp.async.wait_group 0;" ::: "memory")

#define GBAR(g) asm volatile("bar.sync %0, 256;" :: "r"((g) + 1) : "memory")

#define LDSM_X4(r0, r1, r2, r3, a) \
    asm volatile("ldmatrix.sync.aligned.m8n8.x4.shared.b16 {%0,%1,%2,%3}, [%4];" \
        : "=r"(r0), "=r"(r1), "=r"(r2), "=r"(r3) : "r"(a))

#define MMA16816(c, a, b0, b1) \
    asm volatile("mma.sync.aligned.m16n8k16.row.col.f32.f16.f16.f32 " \
        "{%0,%1,%2,%3}, {%4,%5,%6,%7}, {%8,%9}, {%0,%1,%2,%3};" \
        : "+f"((c)[0]), "+f"((c)[1]), "+f"((c)[2]), "+f"((c)[3]) \
        : "r"((a)[0]), "r"((a)[1]), "r"((a)[2]), "r"((a)[3]), "r"(b0), "r"(b1))

// ---------------- combined prep: W swizzle + emb fp16 + pool zero ----------------
__global__ void prep_kernel(const float* __restrict__ conv_w,
                            const float* __restrict__ emb) {
    int idx = blockIdx.x * blockDim.x + threadIdx.x;
    if (idx < KW * FILT * EMB) {       // 49152: weight convert+swizzle
        int k = idx / (FILT * EMB);
        int rem = idx - k * FILT * EMB;
        int f = rem >> 7, e = rem & 127;
        float w = conv_w[(f * EMB + e) * KW + k];
        int dst = k * 16384 + f * 128 + (((e >> 3) ^ (f & 7)) << 3) + (e & 7);
        g_Wh[dst] = __float2half_rn(w);
        // 49152 uint4 = 512*384 uints: zero the pool
        ((uint4*)g_Pool)[idx] = make_uint4(0u, 0u, 0u, 0u);
    }
    if (idx < VOCAB * EMB / 4) {       // 676096: emb fp32 -> fp16
        const float4 x = __ldg((const float4*)emb + idx);
        __half2 h0 = __floats2half2_rn(x.x, x.y);
        __half2 h1 = __floats2half2_rn(x.z, x.w);
        uint2 st;
        st.x = *(uint32_t*)&h0; st.y = *(uint32_t*)&h1;
        *((uint2*)g_EmbH + idx) = st;
    }
}

// ---------------- main kernel: persistent, 2 groups/CTA, unit = 128-l pass ----------------
__global__ __launch_bounds__(512, 1)
void pcnn_hmma_kernel(const int* __restrict__ char_ids,
                      const int* __restrict__ pos_e1,
                      const int* __restrict__ pos_e2,
                      const float* __restrict__ conv_b)
{
    extern __shared__ char smem[];
    const uint32_t sb = smem_u32(smem);
    const int tid  = threadIdx.x;
    const int g    = tid >> 8;          // group 0/1
    const int gtid = tid & 255;
    const int w    = gtid >> 5;
    const int lane = tid & 31;

    const int wf = w & 3;   // f-tile: f in [wf*32, +32)
    const int wl = w >> 2;  // l-tile: l_local in [wl*64, +64)

    const uint32_t mbar = sb + MBAR_OFF;

    // resident W copy (96 KB, once per CTA for the whole kernel)
    if (tid == 0) {
        MBAR_INIT(mbar, 1);
        MBAR_EXPECT_TX(mbar, WS_BYTES);
        BULK_G2S(sb + WS_OFF, (uint64_t)&g_Wh[0], WS_BYTES, mbar);
    }
    __syncthreads();

    // epilogue constants (batch-independent)
    const int rowc = lane >> 2;
    const int colc = (lane & 3) * 2;
    float biasv[4];
    #pragma unroll
    for (int i = 0; i < 4; ++i)
        biasv[i] = conv_b[wf * 32 + (i >> 1) * 16 + rowc + (i & 1) * 8];
    float rm[4][3];
    #pragma unroll
    for (int i = 0; i < 4; ++i) { rm[i][0] = 0.f; rm[i][1] = 0.f; rm[i][2] = 0.f; }

    // ldmatrix lane-address components
    const int a_row = lane & 15;
    const int a_cg  = lane >> 4;
    const int b_r  = (lane & 7) + ((lane >> 4) << 3);
    const int b_kc = (lane >> 3) & 1;

    const uint32_t xsb[2] = {sb + (uint32_t)XS_OFF(g, 0), sb + (uint32_t)XS_OFF(g, 1)};

    // async gather of tile (batch bb, l-base pb) into buffer d: 130 rows x 16 chunks
    #define ISSUE_GATHER(bb, pb, d) do { \
        _Pragma("unroll") \
        for (int it = 0; it < 9; ++it) { \
            const int v = gtid + it * 256; \
            if (v < 130 * 16) { \
                const int p = v >> 4, c = v & 15; \
                const int l = (pb) + p - 1; \
                const int ok = (l >= 0 && l < SEQ); \
                const int lc = ok ? l : 0; \
                const int id = __ldg(&char_ids[(bb) * SEQ + lc]); \
                const uint64_t src = (uint64_t)&g_EmbH[(size_t)id * EMB] + (uint32_t)(c << 4); \
                const uint32_t dst = xsb[d] + (uint32_t)(p * 256 + ((c ^ (p & 7)) << 4)); \
                CP_ASYNC16(dst, src, ok ? 16 : 0); \
            } \
        } \
        CP_COMMIT(); \
    } while (0)

    // static schedule: slot handles units slot, slot+nslots, ...
    const int nslots = (int)gridDim.x * 2;
    const int slot = blockIdx.x * 2 + g;

    int cu = slot;
    bool valid = (cu < NUNITS);
    if (valid) ISSUE_GATHER(cu >> 2, (cu & 3) * 128, 0);
    CP_WAIT0();
    MBAR_WAIT(mbar, 0u);
    GBAR(g);

    int buf = 0;
    while (valid) {
        const int batch = cu >> 2;
        const int pbase = (cu & 3) * 128;

        // segment bounds for this batch
        const int p1 = __ldg(&pos_e1[batch]), p2 = __ldg(&pos_e2[batch]);
        int e1 = min(p1, p2), e2 = max(p1, p2);
        if (e1 == e2) e2 = min(e1 + 1, SEQ);
        const int m1hi = max(e1, 1);
        const int m3lo = min(e2, SEQ - 1);

        // prefetch next unit
        const int nu = cu + nslots;
        const bool nvalid = (nu < NUNITS);
        if (nvalid) ISSUE_GATHER(nu >> 2, (nu & 3) * 128, buf ^ 1);

        // ---- GEMM: C[32f x 64l] += sum_k sum_e W[k] * X(shifted by k) ----
        float acc[2][8][4];
        #pragma unroll
        for (int mt = 0; mt < 2; ++mt)
            #pragma unroll
            for (int nt = 0; nt < 8; ++nt)
                #pragma unroll
                for (int i = 0; i < 4; ++i) acc[mt][nt][i] = 0.f;

        #pragma unroll
        for (int k = 0; k < KW; ++k) {
            const uint32_t wsBase = sb + WS_OFF + (uint32_t)k * 32768u;
            uint32_t aBase[2]; int aS[2];
            #pragma unroll
            for (int mt = 0; mt < 2; ++mt) {
                const int f = wf * 32 + mt * 16 + a_row;
                aBase[mt] = wsBase + (uint32_t)f * 256u;
                aS[mt] = f & 7;
            }
            const int p0 = wl * 64 + b_r + k;
            const uint32_t bBase = xsb[buf] + (uint32_t)p0 * 256u;
            const int bS = p0 & 7;

            #pragma unroll
            for (int ec = 0; ec < 8; ++ec) {
                uint32_t a0[4], a1[4], bb[4][4];
                const int ca = ec * 2 + a_cg;
                const int cb = ec * 2 + b_kc;
                LDSM_X4(a0[0], a0[1], a0[2], a0[3],
                        aBase[0] + (uint32_t)((ca ^ aS[0]) << 4));
                LDSM_X4(a1[0], a1[1], a1[2], a1[3],
                        aBase[1] + (uint32_t)((ca ^ aS[1]) << 4));
                const uint32_t bsw = (uint32_t)((cb ^ bS) << 4);
                #pragma unroll
                for (int q = 0; q < 4; ++q)
                    LDSM_X4(bb[q][0], bb[q][1], bb[q][2], bb[q][3],
                            bBase + (uint32_t)(q * 4096) + bsw);

                #pragma unroll
                for (int q = 0; q < 4; ++q) {
                    MMA16816(acc[0][2 * q],     a0, bb[q][0], bb[q][1]);
                    MMA16816(acc[0][2 * q + 1], a0, bb[q][2], bb[q][3]);
                    MMA16816(acc[1][2 * q],     a1, bb[q][0], bb[q][1]);
                    MMA16816(acc[1][2 * q + 1], a1, bb[q][2], bb[q][3]);
                }
            }
        }

        // ---- epilogue: bias + ReLU + running segment max ----
        #pragma unroll
        for (int mt = 0; mt < 2; ++mt)
            #pragma unroll
            for (int nt = 0; nt < 8; ++nt)
                #pragma unroll
                for (int e = 0; e < 4; ++e) {
                    const int half = e >> 1;
                    const int idx = mt * 2 + half;
                    float v = acc[mt][nt][e] + biasv[idx];
                    v = fmaxf(v, 0.f);
                    const int l = pbase + wl * 64 + nt * 8 + colc + (e & 1);
                    if (l < m1hi)          rm[idx][0] = fmaxf(rm[idx][0], v);
                    if (l >= e1 && l < e2) rm[idx][1] = fmaxf(rm[idx][1], v);
                    if (l >= m3lo)         rm[idx][2] = fmaxf(rm[idx][2], v);
                }

        // ---- unit end: flush register maxima to global pool (REDG, skip zeros) ----
        {
            unsigned* pb_ = &g_Pool[batch * 3 * FILT];
            #pragma unroll
            for (int i = 0; i < 4; ++i) {
                const int f = wf * 32 + (i >> 1) * 16 + rowc + (i & 1) * 8;
                if (rm[i][0] > 0.f) atomicMax(&pb_[f],            __float_as_uint(rm[i][0]));
                if (rm[i][1] > 0.f) atomicMax(&pb_[FILT + f],     __float_as_uint(rm[i][1]));
                if (rm[i][2] > 0.f) atomicMax(&pb_[2 * FILT + f], __float_as_uint(rm[i][2]));
                rm[i][0] = 0.f; rm[i][1] = 0.f; rm[i][2] = 0.f;
            }
        }

        CP_WAIT0();   // next buffer landed
        GBAR(g);      // group done reading buf; cp.async stores visible
        buf ^= 1;
        cu = nu; valid = nvalid;
    }
}

// ---------------- FC kernel: out[b][c] = pooled . fc_w[c] + fc_b[c] ----------------
__global__ __launch_bounds__(64, 8)
void fc_kernel(const float* __restrict__ fc_w,
               const float* __restrict__ fc_b,
               float* __restrict__ out) {
    const int b = blockIdx.x;
    const int c = threadIdx.x;
    if (c < NCLS) {
        float a = fc_b[c];
        const unsigned* pp = &g_Pool[b * 3 * FILT];
        const float* wv = &fc_w[c * 3 * FILT];
        #pragma unroll 8
        for (int i = 0; i < 3 * FILT; ++i)
            a = fmaf(__uint_as_float(pp[i]), __ldg(&wv[i]), a);
        out[b * NCLS + c] = a;
    }
}

extern "C" void kernel_launch(void* const* d_in, const int* in_sizes, int n_in,
                              void* d_out, int out_size) {
    const int*   char_ids = (const int*)  d_in[0];
    const int*   pos_e1   = (const int*)  d_in[1];
    const int*   pos_e2   = (const int*)  d_in[2];
    const float* emb      = (const float*)d_in[3];
    const float* conv_w   = (const float*)d_in[4];
    const float* conv_b   = (const float*)d_in[5];
    const float* fc_w     = (const float*)d_in[6];
    const float* fc_b     = (const float*)d_in[7];
    float* out = (float*)d_out;

    cudaFuncSetAttribute(pcnn_hmma_kernel,
                         cudaFuncAttributeMaxDynamicSharedMemorySize, SMEM_BYTES);

    prep_kernel<<<(VOCAB * EMB / 4 + 255) / 256, 256>>>(conv_w, emb);
    pcnn_hmma_kernel<<<152, 512, SMEM_BYTES>>>(char_ids, pos_e1, pos_e2, conv_b);
    fc_kernel<<<BATCH, 64>>>(fc_w, fc_b, out);
}